// round 2
// baseline (speedup 1.0000x reference)
#include <cuda_runtime.h>
#include <cstdint>
#include <cstdio>

#define B_ 16
#define T_ 4096
#define D_ 1024
#define C_ 128
#define M_ (B_*T_)        // 65536 tokens
#define GROUPS 8          // row-groups for recurrence parallelism

// ---------------- scratch (static device globals; no allocation) -------------
__device__ float g_q[(size_t)M_*C_];
__device__ float g_k[(size_t)M_*C_];
__device__ float g_v[(size_t)M_*C_];
__device__ float g_g[(size_t)M_*C_];
__device__ float g_a[M_];
__device__ float g_b[M_];
__device__ float g_opart[(size_t)GROUPS*M_*C_];
__device__ float g_o[(size_t)M_*C_];

__device__ __forceinline__ float sigmoidf_(float x) { return 1.0f / (1.0f + expf(-x)); }

// =============================================================================
// GEMM (NT): C[m][n] = sum_k A[m][k] * B[n][k] + bias[n]
// A: MxK row-major, B: NxK row-major. Tile 64x128, KT=16, 256 threads,
// double-buffered smem, one barrier per k-iter. EPI: 0 = none, 1 = sigmoid.
// Requires M%64==0, N%128==0, K%16==0 (true for all our shapes).
// =============================================================================
template<int EPI>
__global__ __launch_bounds__(256) void gemm_nt(const float* __restrict__ A,
                                               const float* __restrict__ Bm,
                                               const float* __restrict__ bias,
                                               float* __restrict__ C,
                                               int M, int N, int K)
{
    constexpr int MT = 64, NT = 128, KT = 16;
    __shared__ __align__(16) float sA[2][KT][MT];
    __shared__ __align__(16) float sB[2][KT][NT];

    const int tid = threadIdx.x;
    const int m0  = blockIdx.x * MT;
    const int n0  = blockIdx.y * NT;

    // loader mapping: 256 threads, each loads one float4 of A and two of B
    const int lr = tid >> 2;          // 0..63
    const int lk = (tid & 3) << 2;    // 0,4,8,12

    // compute mapping: micro-tile 8 rows x 4 cols
    const int tx = tid & 31;          // cols: tx*4 .. tx*4+3
    const int ty = tid >> 5;          // rows: ty*8 .. ty*8+7

    float acc[8][4];
#pragma unroll
    for (int r = 0; r < 8; ++r)
#pragma unroll
        for (int c = 0; c < 4; ++c) acc[r][c] = 0.0f;

    const int NIT = K / KT;
    const float* pA  = A  + (size_t)(m0 + lr) * K + lk;
    const float* pB0 = Bm + (size_t)(n0 + lr) * K + lk;
    const float* pB1 = Bm + (size_t)(n0 + lr + 64) * K + lk;

    float4 ra  = *(const float4*)pA;
    float4 rb0 = *(const float4*)pB0;
    float4 rb1 = *(const float4*)pB1;

    for (int it = 0; it < NIT; ++it) {
        const int buf = it & 1;
        sA[buf][lk+0][lr] = ra.x;  sA[buf][lk+1][lr] = ra.y;
        sA[buf][lk+2][lr] = ra.z;  sA[buf][lk+3][lr] = ra.w;
        sB[buf][lk+0][lr] = rb0.x; sB[buf][lk+1][lr] = rb0.y;
        sB[buf][lk+2][lr] = rb0.z; sB[buf][lk+3][lr] = rb0.w;
        sB[buf][lk+0][lr+64] = rb1.x; sB[buf][lk+1][lr+64] = rb1.y;
        sB[buf][lk+2][lr+64] = rb1.z; sB[buf][lk+3][lr+64] = rb1.w;
        __syncthreads();

        if (it + 1 < NIT) {
            const int ko = (it + 1) * KT;
            ra  = *(const float4*)(pA  + ko);
            rb0 = *(const float4*)(pB0 + ko);
            rb1 = *(const float4*)(pB1 + ko);
        }

#pragma unroll
        for (int kk = 0; kk < KT; ++kk) {
            float4 a0 = *(const float4*)&sA[buf][kk][ty*8];
            float4 a1 = *(const float4*)&sA[buf][kk][ty*8+4];
            float4 b0 = *(const float4*)&sB[buf][kk][tx*4];
            float av[8] = {a0.x,a0.y,a0.z,a0.w,a1.x,a1.y,a1.z,a1.w};
            float bv[4] = {b0.x,b0.y,b0.z,b0.w};
#pragma unroll
            for (int r = 0; r < 8; ++r)
#pragma unroll
                for (int c = 0; c < 4; ++c)
                    acc[r][c] += av[r] * bv[c];
        }
        // no trailing barrier needed: next iter's STS targets the other buffer,
        // and the buffer is only re-written two iters later, past the next barrier.
    }

    const int nc = n0 + tx * 4;
    float b0v = bias[nc+0], b1v = bias[nc+1], b2v = bias[nc+2], b3v = bias[nc+3];
#pragma unroll
    for (int r = 0; r < 8; ++r) {
        size_t m = (size_t)(m0 + ty*8 + r);
        float4 o4;
        o4.x = acc[r][0] + b0v;
        o4.y = acc[r][1] + b1v;
        o4.z = acc[r][2] + b2v;
        o4.w = acc[r][3] + b3v;
        if (EPI == 1) {
            o4.x = sigmoidf_(o4.x); o4.y = sigmoidf_(o4.y);
            o4.z = sigmoidf_(o4.z); o4.w = sigmoidf_(o4.w);
        }
        *(float4*)(C + m * N + nc) = o4;
    }
}

// =============================================================================
// alpha/beta: per-token dot over D=1024 with Wa/Wb, + bias, sigmoid.
// One warp per token, 8 tokens per 256-thread CTA. Wa/Wb staged in smem.
// =============================================================================
__global__ __launch_bounds__(256) void ab_kernel(const float* __restrict__ x,
                                                 const float* __restrict__ Wa,
                                                 const float* __restrict__ ba,
                                                 const float* __restrict__ Wb,
                                                 const float* __restrict__ bb,
                                                 float* __restrict__ a_out,
                                                 float* __restrict__ b_out)
{
    __shared__ __align__(16) float sWa[D_];
    __shared__ __align__(16) float sWb[D_];
    const int tid = threadIdx.x;
    for (int i = tid; i < D_; i += 256) { sWa[i] = Wa[i]; sWb[i] = Wb[i]; }
    __syncthreads();

    const int warp = tid >> 5, lane = tid & 31;
    const int tok  = blockIdx.x * 8 + warp;
    const float* xr = x + (size_t)tok * D_;

    float da = 0.0f, db = 0.0f;
#pragma unroll
    for (int j = 0; j < 8; ++j) {
        float4 xv = *(const float4*)(xr  + j*128 + lane*4);
        float4 wa = *(const float4*)(sWa + j*128 + lane*4);
        float4 wb = *(const float4*)(sWb + j*128 + lane*4);
        da += xv.x*wa.x + xv.y*wa.y + xv.z*wa.z + xv.w*wa.w;
        db += xv.x*wb.x + xv.y*wb.y + xv.z*wb.z + xv.w*wb.w;
    }
#pragma unroll
    for (int off = 16; off > 0; off >>= 1) {
        da += __shfl_xor_sync(0xffffffffu, da, off);
        db += __shfl_xor_sync(0xffffffffu, db, off);
    }
    if (lane == 0) {
        a_out[tok] = sigmoidf_(da + ba[0]);
        b_out[tok] = sigmoidf_(db + bb[0]);
    }
}

// =============================================================================
// k row-normalization: k /= max(||k||, 1e-12). One warp per row (C=128).
// =============================================================================
__global__ __launch_bounds__(256) void knorm_kernel(float* __restrict__ k)
{
    const int tid  = threadIdx.x;
    const int lane = tid & 31;
    const size_t row = (size_t)blockIdx.x * 8 + (tid >> 5);
    float4 kv = *(const float4*)(k + row * C_ + lane * 4);
    float ss = kv.x*kv.x + kv.y*kv.y + kv.z*kv.z + kv.w*kv.w;
#pragma unroll
    for (int off = 16; off > 0; off >>= 1)
        ss += __shfl_xor_sync(0xffffffffu, ss, off);
    float inv = 1.0f / fmaxf(sqrtf(ss), 1e-12f);
    kv.x *= inv; kv.y *= inv; kv.z *= inv; kv.w *= inv;
    *(float4*)(k + row * C_ + lane * 4) = kv;
}

// =============================================================================
// Gated delta-rule recurrence, row-partitioned across GROUPS CTAs per batch.
// Grid (GROUPS, B). Each CTA owns 16 rows of S (16x128 fp32, in registers).
//   thread layout: 256 threads = 8 warps; row_local = warp*2 + (lane>>4),
//   column group cg = lane&15 -> 8 columns per thread.
// Per step:  d_i = S_i . k  (shfl-reduce over 16 lanes)
//            c_i = b*v_i - a*b*d_i ;  S_ij = a*S_ij + c_i*k_j
//            partial o_j = sum_{i in group} q_i*S_ij  -> written to g_opart.
// No cross-CTA sync; groups are summed by combine_kernel afterwards.
// =============================================================================
__global__ __launch_bounds__(256) void recurrence_kernel(const float* __restrict__ q,
                                                         const float* __restrict__ k,
                                                         const float* __restrict__ v,
                                                         const float* __restrict__ al,
                                                         const float* __restrict__ be,
                                                         float* __restrict__ opart)
{
    const int g   = blockIdx.x;   // row group 0..7
    const int bb  = blockIdx.y;   // batch 0..15
    const int tid = threadIdx.x;
    const int warp = tid >> 5, lane = tid & 31;
    const int rl = warp * 2 + (lane >> 4);   // local row 0..15
    const int i  = g * 16 + rl;              // global row (v/q index)
    const int jb = (lane & 15) * 8;          // first owned column

    float S[8];
#pragma unroll
    for (int jj = 0; jj < 8; ++jj) S[jj] = 0.0f;

    __shared__ __align__(16) float osh[2][8][C_];

    const size_t bbase = (size_t)bb * T_ * C_;
    const size_t sbase = (size_t)bb * T_;
    float* op = opart + (size_t)g * M_ * C_ + bbase;

    // prefetch t = 0
    float4 kn0 = *(const float4*)(k + bbase + jb);
    float4 kn1 = *(const float4*)(k + bbase + jb + 4);
    float  qn  = q[bbase + i];
    float  vn  = v[bbase + i];
    float  an  = al[sbase];
    float  bn  = be[sbase];

#pragma unroll 1
    for (int t = 0; t < T_; ++t) {
        const float4 k0 = kn0, k1 = kn1;
        const float qi = qn, vi = vn, at = an, bt = bn;

        if (t + 1 < T_) {
            const size_t nb = bbase + (size_t)(t + 1) * C_;
            kn0 = *(const float4*)(k + nb + jb);
            kn1 = *(const float4*)(k + nb + jb + 4);
            qn  = q[nb + i];
            vn  = v[nb + i];
            an  = al[sbase + t + 1];
            bn  = be[sbase + t + 1];
        }

        const float kr[8] = {k0.x,k0.y,k0.z,k0.w,k1.x,k1.y,k1.z,k1.w};

        // d = S_i . k  over the 16 lanes of this row
        float d = 0.0f;
#pragma unroll
        for (int jj = 0; jj < 8; ++jj) d += S[jj] * kr[jj];
        d += __shfl_xor_sync(0xffffffffu, d, 8);
        d += __shfl_xor_sync(0xffffffffu, d, 4);
        d += __shfl_xor_sync(0xffffffffu, d, 2);
        d += __shfl_xor_sync(0xffffffffu, d, 1);

        const float c = bt * vi - at * bt * d;

        float po[8];
#pragma unroll
        for (int jj = 0; jj < 8; ++jj) {
            S[jj]  = at * S[jj] + c * kr[jj];
            po[jj] = qi * S[jj];
        }

        // sum the 2 rows living in this warp (lanes differing in bit 4)
#pragma unroll
        for (int jj = 0; jj < 8; ++jj)
            po[jj] += __shfl_xor_sync(0xffffffffu, po[jj], 16);

        const int buf = t & 1;
        if (lane < 16) {
            *(float4*)&osh[buf][warp][lane*8]     = make_float4(po[0],po[1],po[2],po[3]);
            *(float4*)&osh[buf][warp][lane*8 + 4] = make_float4(po[4],po[5],po[6],po[7]);
        }
        __syncthreads();   // single barrier per step; osh double-buffered

        if (tid < C_) {
            float oo = 0.0f;
#pragma unroll
            for (int w = 0; w < 8; ++w) oo += osh[buf][w][tid];
            op[(size_t)t * C_ + tid] = oo;
        }
    }
}

// =============================================================================
// combine: o = (sum over groups of opart) * gate   (gate already sigmoided)
// =============================================================================
__global__ __launch_bounds__(256) void combine_kernel(const float* __restrict__ opart,
                                                      const float* __restrict__ gate,
                                                      float* __restrict__ o)
{
    const size_t idx = ((size_t)blockIdx.x * 256 + threadIdx.x) * 4;
    float4 s = make_float4(0.f, 0.f, 0.f, 0.f);
#pragma unroll
    for (int g = 0; g < GROUPS; ++g) {
        float4 p = *(const float4*)(opart + (size_t)g * M_ * C_ + idx);
        s.x += p.x; s.y += p.y; s.z += p.z; s.w += p.w;
    }
    float4 gt = *(const float4*)(gate + idx);
    s.x *= gt.x; s.y *= gt.y; s.z *= gt.z; s.w *= gt.w;
    *(float4*)(o + idx) = s;
}

// =============================================================================
extern "C" void kernel_launch(void* const* d_in, const int* in_sizes, int n_in,
                              void* d_out, int out_size)
{
    const float* x  = (const float*)d_in[0];
    const float* Wq = (const float*)d_in[1];
    const float* bq = (const float*)d_in[2];
    const float* Wk = (const float*)d_in[3];
    const float* bk = (const float*)d_in[4];
    const float* Wv = (const float*)d_in[5];
    const float* bv = (const float*)d_in[6];
    const float* Wa = (const float*)d_in[7];
    const float* ba = (const float*)d_in[8];
    const float* Wb = (const float*)d_in[9];
    const float* bb = (const float*)d_in[10];
    const float* Wg = (const float*)d_in[11];
    const float* bg = (const float*)d_in[12];
    const float* Wo = (const float*)d_in[13];
    const float* bo = (const float*)d_in[14];
    float* out = (float*)d_out;

    float *q, *k, *v, *g, *a, *b, *op, *o;
    cudaGetSymbolAddress((void**)&q,  g_q);
    cudaGetSymbolAddress((void**)&k,  g_k);
    cudaGetSymbolAddress((void**)&v,  g_v);
    cudaGetSymbolAddress((void**)&g,  g_g);
    cudaGetSymbolAddress((void**)&a,  g_a);
    cudaGetSymbolAddress((void**)&b,  g_b);
    cudaGetSymbolAddress((void**)&op, g_opart);
    cudaGetSymbolAddress((void**)&o,  g_o);

    const dim3 blk(256);

    // projections (M=65536, N=128, K=1024)
    gemm_nt<0><<<dim3(M_/64, C_/128), blk>>>(x, Wq, bq, q, M_, C_, D_);
    gemm_nt<0><<<dim3(M_/64, C_/128), blk>>>(x, Wk, bk, k, M_, C_, D_);
    gemm_nt<0><<<dim3(M_/64, C_/128), blk>>>(x, Wv, bv, v, M_, C_, D_);
    gemm_nt<1><<<dim3(M_/64, C_/128), blk>>>(x, Wg, bg, g, M_, C_, D_);  // sigmoid epilogue

    // alpha/beta scalars
    ab_kernel<<<M_/8, blk>>>(x, Wa, ba, Wb, bb, a, b);

    // k row normalization
    knorm_kernel<<<M_/8, blk>>>(k);

    // sequential recurrence, row-partitioned (128 CTAs, no cross-CTA sync)
    recurrence_kernel<<<dim3(GROUPS, B_), blk>>>(q, k, v, a, b, op);

    // group-sum + gate
    combine_kernel<<<(M_*C_/4)/256, blk>>>(op, g, o);

    // output projection (M=65536, N=1024, K=128)
    gemm_nt<0><<<dim3(M_/64, D_/128), blk>>>(o, Wo, bo, out, M_, D_, C_);
}

// round 3
// speedup vs baseline: 1.3942x; 1.3942x over previous
#include <cuda_runtime.h>
#include <cstdint>

#define B_ 16
#define T_ 4096
#define D_ 1024
#define C_ 128
#define M_ (B_*T_)        // 65536 tokens
#define GROUPS 8          // row-groups for recurrence parallelism
#define LCH 4             // chunk length inside recurrence

// ---------------- scratch (static device globals; no allocation) -------------
__device__ float g_q[(size_t)M_*C_];
__device__ float g_k[(size_t)M_*C_];
__device__ float g_v[(size_t)M_*C_];
__device__ float g_g[(size_t)M_*C_];
__device__ float g_a[M_];
__device__ float g_b[M_];
__device__ float g_opart[(size_t)GROUPS*M_*C_];
__device__ float g_o[(size_t)M_*C_];

__device__ __forceinline__ float sigmoidf_(float x) { return 1.0f / (1.0f + expf(-x)); }

// =============================================================================
// GEMM (NT): C[m][n] = sum_k A[m][k]*B[n][k] + bias[n]
// 128x128 tile, KT=8, 256 threads, 8x8 micro-tile (4+4 split), double-buffered.
// EPI: 0 none, 1 sigmoid, 2 row-L2-normalize (requires N == 128 per tile row).
// Requires M%128==0, N%128==0, K%8==0.
// =============================================================================
template<int EPI>
__global__ __launch_bounds__(256, 2) void gemm128(const float* __restrict__ A,
                                                  const float* __restrict__ Bm,
                                                  const float* __restrict__ bias,
                                                  float* __restrict__ C,
                                                  int M, int N, int K)
{
    constexpr int KT = 8;
    __shared__ __align__(16) float sA[2][KT][128];
    __shared__ __align__(16) float sB[2][KT][128];

    const int tid = threadIdx.x;
    const int m0  = blockIdx.x * 128;
    const int n0  = blockIdx.y * 128;

    // loader: each thread loads one float4 of A and one of B per k-iter
    const int lr = tid & 127;
    const int lk = (tid >> 7) << 2;     // 0 or 4

    // compute: 16x16 thread grid, 8x8 micro-tile as 4+4 split
    const int tx = tid & 15;
    const int ty = tid >> 4;

    float acc[2][4][2][4];
#pragma unroll
    for (int rg = 0; rg < 2; ++rg)
#pragma unroll
        for (int r = 0; r < 4; ++r)
#pragma unroll
            for (int cg = 0; cg < 2; ++cg)
#pragma unroll
                for (int c = 0; c < 4; ++c) acc[rg][r][cg][c] = 0.0f;

    const int NIT = K / KT;
    const float* pA = A  + (size_t)(m0 + lr) * K + lk;
    const float* pB = Bm + (size_t)(n0 + lr) * K + lk;

    float4 ra = *(const float4*)pA;
    float4 rb = *(const float4*)pB;

    for (int it = 0; it < NIT; ++it) {
        const int buf = it & 1;
        sA[buf][lk+0][lr] = ra.x; sA[buf][lk+1][lr] = ra.y;
        sA[buf][lk+2][lr] = ra.z; sA[buf][lk+3][lr] = ra.w;
        sB[buf][lk+0][lr] = rb.x; sB[buf][lk+1][lr] = rb.y;
        sB[buf][lk+2][lr] = rb.z; sB[buf][lk+3][lr] = rb.w;
        __syncthreads();

        if (it + 1 < NIT) {
            const int ko = (it + 1) * KT;
            ra = *(const float4*)(pA + ko);
            rb = *(const float4*)(pB + ko);
        }

#pragma unroll
        for (int kk = 0; kk < KT; ++kk) {
            float4 a0 = *(const float4*)&sA[buf][kk][ty*4];
            float4 a1 = *(const float4*)&sA[buf][kk][64 + ty*4];
            float4 b0 = *(const float4*)&sB[buf][kk][tx*4];
            float4 b1 = *(const float4*)&sB[buf][kk][64 + tx*4];
            float av[2][4] = {{a0.x,a0.y,a0.z,a0.w},{a1.x,a1.y,a1.z,a1.w}};
            float bv[2][4] = {{b0.x,b0.y,b0.z,b0.w},{b1.x,b1.y,b1.z,b1.w}};
#pragma unroll
            for (int rg = 0; rg < 2; ++rg)
#pragma unroll
                for (int r = 0; r < 4; ++r)
#pragma unroll
                    for (int cg = 0; cg < 2; ++cg)
#pragma unroll
                        for (int c = 0; c < 4; ++c)
                            acc[rg][r][cg][c] += av[rg][r] * bv[cg][c];
        }
        // single barrier per iter: writes to this buffer recur only two iters
        // later, beyond the next barrier.
    }

    // ---------------- epilogue ----------------
    float4 bb0 = *(const float4*)&bias[n0 + tx*4];
    float4 bb1 = *(const float4*)&bias[n0 + 64 + tx*4];
    const float bvv[2][4] = {{bb0.x,bb0.y,bb0.z,bb0.w},{bb1.x,bb1.y,bb1.z,bb1.w}};

#pragma unroll
    for (int rg = 0; rg < 2; ++rg)
#pragma unroll
        for (int r = 0; r < 4; ++r)
#pragma unroll
            for (int cg = 0; cg < 2; ++cg)
#pragma unroll
                for (int c = 0; c < 4; ++c)
                    acc[rg][r][cg][c] += bvv[cg][c];

    if (EPI == 1) {
#pragma unroll
        for (int rg = 0; rg < 2; ++rg)
#pragma unroll
            for (int r = 0; r < 4; ++r)
#pragma unroll
                for (int cg = 0; cg < 2; ++cg)
#pragma unroll
                    for (int c = 0; c < 4; ++c)
                        acc[rg][r][cg][c] = sigmoidf_(acc[rg][r][cg][c]);
    }

    if (EPI == 2) {
        // row L2 norm: 16 threads with same ty (lanes differing in bits 0-3)
        // jointly hold all 128 columns of each of the 8 rows.
#pragma unroll
        for (int rg = 0; rg < 2; ++rg)
#pragma unroll
            for (int r = 0; r < 4; ++r) {
                float ss = 0.0f;
#pragma unroll
                for (int cg = 0; cg < 2; ++cg)
#pragma unroll
                    for (int c = 0; c < 4; ++c)
                        ss += acc[rg][r][cg][c] * acc[rg][r][cg][c];
                ss += __shfl_xor_sync(0xffffffffu, ss, 1);
                ss += __shfl_xor_sync(0xffffffffu, ss, 2);
                ss += __shfl_xor_sync(0xffffffffu, ss, 4);
                ss += __shfl_xor_sync(0xffffffffu, ss, 8);
                const float inv = 1.0f / fmaxf(sqrtf(ss), 1e-12f);
#pragma unroll
                for (int cg = 0; cg < 2; ++cg)
#pragma unroll
                    for (int c = 0; c < 4; ++c)
                        acc[rg][r][cg][c] *= inv;
            }
    }

#pragma unroll
    for (int rg = 0; rg < 2; ++rg)
#pragma unroll
        for (int r = 0; r < 4; ++r) {
            const size_t row = (size_t)(m0 + rg*64 + ty*4 + r);
#pragma unroll
            for (int cg = 0; cg < 2; ++cg) {
                float4 o4 = make_float4(acc[rg][r][cg][0], acc[rg][r][cg][1],
                                        acc[rg][r][cg][2], acc[rg][r][cg][3]);
                *(float4*)(C + row * N + n0 + cg*64 + tx*4) = o4;
            }
        }
}

// =============================================================================
// alpha/beta: per-token dot over D with Wa/Wb, + bias, sigmoid.
// =============================================================================
__global__ __launch_bounds__(256) void ab_kernel(const float* __restrict__ x,
                                                 const float* __restrict__ Wa,
                                                 const float* __restrict__ ba,
                                                 const float* __restrict__ Wb,
                                                 const float* __restrict__ bb,
                                                 float* __restrict__ a_out,
                                                 float* __restrict__ b_out)
{
    __shared__ __align__(16) float sWa[D_];
    __shared__ __align__(16) float sWb[D_];
    const int tid = threadIdx.x;
    for (int i = tid; i < D_; i += 256) { sWa[i] = Wa[i]; sWb[i] = Wb[i]; }
    __syncthreads();

    const int warp = tid >> 5, lane = tid & 31;
    const int tok  = blockIdx.x * 8 + warp;
    const float* xr = x + (size_t)tok * D_;

    float da = 0.0f, db = 0.0f;
#pragma unroll
    for (int j = 0; j < 8; ++j) {
        float4 xv = *(const float4*)(xr  + j*128 + lane*4);
        float4 wa = *(const float4*)(sWa + j*128 + lane*4);
        float4 wb = *(const float4*)(sWb + j*128 + lane*4);
        da += xv.x*wa.x + xv.y*wa.y + xv.z*wa.z + xv.w*wa.w;
        db += xv.x*wb.x + xv.y*wb.y + xv.z*wb.z + xv.w*wb.w;
    }
#pragma unroll
    for (int off = 16; off > 0; off >>= 1) {
        da += __shfl_xor_sync(0xffffffffu, da, off);
        db += __shfl_xor_sync(0xffffffffu, db, off);
    }
    if (lane == 0) {
        a_out[tok] = sigmoidf_(da + ba[0]);
        b_out[tok] = sigmoidf_(db + bb[0]);
    }
}

// =============================================================================
// Chunked (L=4) gated delta-rule recurrence, row-partitioned.
// Grid (GROUPS, B). 16 rows of S per CTA (registers): 256 threads, 8 warps,
// row = warp*2 + (lane>>4), cols = (lane&15)*8 .. +7.
//
// Per chunk: m_tau = S.k_tau (chunk-start S) and Gram G[s][tau] = k_s.k_tau
// are reduced as ONE batch of 10 independent butterfly reductions; an exact
// scalar recursion recovers c_tau; then 4 register-resident rank-1 updates and
// o-partials with a single __syncthreads per chunk.
// =============================================================================
struct ChunkRegs {
    float k[LCH][8];
    float q[LCH], v[LCH], a[LCH], b[LCH];
};

__device__ __forceinline__ float red16(float x) {
    x += __shfl_xor_sync(0xffffffffu, x, 1);
    x += __shfl_xor_sync(0xffffffffu, x, 2);
    x += __shfl_xor_sync(0xffffffffu, x, 4);
    x += __shfl_xor_sync(0xffffffffu, x, 8);
    return x;
}

__device__ __forceinline__ void load_chunk(int tcN,
                                           const float* __restrict__ kg,
                                           const float* __restrict__ qg,
                                           const float* __restrict__ vg,
                                           const float* __restrict__ ag,
                                           const float* __restrict__ bg,
                                           int i, int jb, ChunkRegs& R)
{
#pragma unroll
    for (int t4 = 0; t4 < LCH; ++t4) {
        const size_t off = ((size_t)tcN*LCH + t4) * C_;
        float4 x0 = *(const float4*)(kg + off + jb);
        float4 x1 = *(const float4*)(kg + off + jb + 4);
        R.k[t4][0]=x0.x; R.k[t4][1]=x0.y; R.k[t4][2]=x0.z; R.k[t4][3]=x0.w;
        R.k[t4][4]=x1.x; R.k[t4][5]=x1.y; R.k[t4][6]=x1.z; R.k[t4][7]=x1.w;
        R.q[t4] = qg[off + i];
        R.v[t4] = vg[off + i];
    }
    float4 a4 = *(const float4*)(ag + tcN*LCH);
    float4 b4 = *(const float4*)(bg + tcN*LCH);
    R.a[0]=a4.x; R.a[1]=a4.y; R.a[2]=a4.z; R.a[3]=a4.w;
    R.b[0]=b4.x; R.b[1]=b4.y; R.b[2]=b4.z; R.b[3]=b4.w;
}

__device__ __forceinline__ void chunk_body(int tc, int buf, bool pf,
                                           float S[8], ChunkRegs& cur, ChunkRegs& nxt,
                                           const float* __restrict__ kg,
                                           const float* __restrict__ qg,
                                           const float* __restrict__ vg,
                                           const float* __restrict__ ag,
                                           const float* __restrict__ bg,
                                           float* __restrict__ op,
                                           int i, int jb, int warp, int lane, int tid,
                                           float (*osh)[LCH][8][C_])
{
    // --- phase 1: partials vs chunk-start S, plus k-Gram partials ---
    float m[LCH];
#pragma unroll
    for (int t4 = 0; t4 < LCH; ++t4) {
        float s = 0.0f;
#pragma unroll
        for (int jj = 0; jj < 8; ++jj) s += S[jj] * cur.k[t4][jj];
        m[t4] = s;
    }
    float G01=0, G02=0, G03=0, G12=0, G13=0, G23=0;
#pragma unroll
    for (int jj = 0; jj < 8; ++jj) {
        const float k0 = cur.k[0][jj], k1 = cur.k[1][jj];
        const float k2 = cur.k[2][jj], k3 = cur.k[3][jj];
        G01 += k0*k1; G02 += k0*k2; G03 += k0*k3;
        G12 += k1*k2; G13 += k1*k3; G23 += k2*k3;
    }

    // --- prefetch next chunk while reduces are in flight ---
    if (pf) load_chunk(tc + 1, kg, qg, vg, ag, bg, i, jb, nxt);

    // --- one batch of 10 independent reductions ---
    m[0]=red16(m[0]); m[1]=red16(m[1]); m[2]=red16(m[2]); m[3]=red16(m[3]);
    G01=red16(G01); G02=red16(G02); G03=red16(G03);
    G12=red16(G12); G13=red16(G13); G23=red16(G23);

    // --- phase 2: exact scalar recursion for c_tau ---
    const float a0=cur.a[0], a1=cur.a[1], a2=cur.a[2], a3=cur.a[3];
    const float u0 = m[0];
    const float c0 = cur.b[0] * (cur.v[0] - a0*u0);
    const float u1 = a0*m[1] + c0*G01;
    const float c1 = cur.b[1] * (cur.v[1] - a1*u1);
    const float a01 = a0*a1;
    const float u2 = a01*m[2] + a1*c0*G02 + c1*G12;
    const float c2 = cur.b[2] * (cur.v[2] - a2*u2);
    const float u3 = a01*a2*m[3] + a1*a2*c0*G03 + a2*c1*G13 + c2*G23;
    const float c3 = cur.b[3] * (cur.v[3] - a3*u3);
    const float cc[LCH] = {c0, c1, c2, c3};

    // --- phase 3: per-step register updates + o partials (no reduce chains) ---
#pragma unroll
    for (int t4 = 0; t4 < LCH; ++t4) {
        float po[8];
#pragma unroll
        for (int jj = 0; jj < 8; ++jj) {
            S[jj] = cur.a[t4] * S[jj] + cc[t4] * cur.k[t4][jj];
            po[jj] = cur.q[t4] * S[jj];
        }
#pragma unroll
        for (int jj = 0; jj < 8; ++jj)
            po[jj] += __shfl_xor_sync(0xffffffffu, po[jj], 16);
        if (lane < 16) {
            float4* dst = (float4*)&osh[buf][t4][warp][(lane & 15) * 8];
            dst[0] = make_float4(po[0], po[1], po[2], po[3]);
            dst[1] = make_float4(po[4], po[5], po[6], po[7]);
        }
    }
    __syncthreads();   // single barrier per chunk (osh double-buffered)

    // --- phase 4: cross-warp sum + global write (512 slots / 256 threads) ---
#pragma unroll
    for (int ss = 0; ss < 2; ++ss) {
        const int slot = tid + ss * 256;
        const int t4 = slot >> 7, j = slot & 127;
        float oo = 0.0f;
#pragma unroll
        for (int w = 0; w < 8; ++w) oo += osh[buf][t4][w][j];
        op[((size_t)tc*LCH + t4) * C_ + j] = oo;
    }
}

__global__ __launch_bounds__(256) void recurrence4(const float* __restrict__ q,
                                                   const float* __restrict__ k,
                                                   const float* __restrict__ v,
                                                   const float* __restrict__ al,
                                                   const float* __restrict__ be,
                                                   float* __restrict__ opart)
{
    const int g   = blockIdx.x;
    const int bb  = blockIdx.y;
    const int tid = threadIdx.x;
    const int warp = tid >> 5, lane = tid & 31;
    const int rl = warp * 2 + (lane >> 4);
    const int i  = g * 16 + rl;
    const int jb = (lane & 15) * 8;

    __shared__ __align__(16) float osh[2][LCH][8][C_];

    const size_t bbase = (size_t)bb * T_ * C_;
    const size_t sbase = (size_t)bb * T_;
    const float* kg = k + bbase;
    const float* qg = q + bbase;
    const float* vg = v + bbase;
    const float* ag = al + sbase;
    const float* bg = be + sbase;
    float* op = opart + (size_t)g * M_ * C_ + bbase;

    float S[8];
#pragma unroll
    for (int jj = 0; jj < 8; ++jj) S[jj] = 0.0f;

    ChunkRegs RA, RB;
    load_chunk(0, kg, qg, vg, ag, bg, i, jb, RA);

    const int NC = T_ / LCH;   // 1024, even
#pragma unroll 1
    for (int tc = 0; tc < NC; tc += 2) {
        chunk_body(tc,   0, true,          S, RA, RB, kg, qg, vg, ag, bg, op, i, jb, warp, lane, tid, osh);
        chunk_body(tc+1, 1, (tc+2) < NC,   S, RB, RA, kg, qg, vg, ag, bg, op, i, jb, warp, lane, tid, osh);
    }
}

// =============================================================================
// combine: o = (sum over groups of opart) * gate
// =============================================================================
__global__ __launch_bounds__(256) void combine_kernel(const float* __restrict__ opart,
                                                      const float* __restrict__ gate,
                                                      float* __restrict__ o)
{
    const size_t idx = ((size_t)blockIdx.x * 256 + threadIdx.x) * 4;
    float4 s = make_float4(0.f, 0.f, 0.f, 0.f);
#pragma unroll
    for (int g = 0; g < GROUPS; ++g) {
        float4 p = *(const float4*)(opart + (size_t)g * M_ * C_ + idx);
        s.x += p.x; s.y += p.y; s.z += p.z; s.w += p.w;
    }
    float4 gt = *(const float4*)(gate + idx);
    s.x *= gt.x; s.y *= gt.y; s.z *= gt.z; s.w *= gt.w;
    *(float4*)(o + idx) = s;
}

// =============================================================================
extern "C" void kernel_launch(void* const* d_in, const int* in_sizes, int n_in,
                              void* d_out, int out_size)
{
    const float* x  = (const float*)d_in[0];
    const float* Wq = (const float*)d_in[1];
    const float* bq = (const float*)d_in[2];
    const float* Wk = (const float*)d_in[3];
    const float* bk = (const float*)d_in[4];
    const float* Wv = (const float*)d_in[5];
    const float* bv = (const float*)d_in[6];
    const float* Wa = (const float*)d_in[7];
    const float* ba = (const float*)d_in[8];
    const float* Wb = (const float*)d_in[9];
    const float* bb = (const float*)d_in[10];
    const float* Wg = (const float*)d_in[11];
    const float* bg = (const float*)d_in[12];
    const float* Wo = (const float*)d_in[13];
    const float* bo = (const float*)d_in[14];
    float* out = (float*)d_out;

    float *q, *k, *v, *g, *a, *b, *op, *o;
    cudaGetSymbolAddress((void**)&q,  g_q);
    cudaGetSymbolAddress((void**)&k,  g_k);
    cudaGetSymbolAddress((void**)&v,  g_v);
    cudaGetSymbolAddress((void**)&g,  g_g);
    cudaGetSymbolAddress((void**)&a,  g_a);
    cudaGetSymbolAddress((void**)&b,  g_b);
    cudaGetSymbolAddress((void**)&op, g_opart);
    cudaGetSymbolAddress((void**)&o,  g_o);

    const dim3 blk(256);

    // projections (M=65536, N=128, K=1024); k-norm fused into k's epilogue
    gemm128<0><<<dim3(M_/128, 1), blk>>>(x, Wq, bq, q, M_, C_, D_);
    gemm128<2><<<dim3(M_/128, 1), blk>>>(x, Wk, bk, k, M_, C_, D_);
    gemm128<0><<<dim3(M_/128, 1), blk>>>(x, Wv, bv, v, M_, C_, D_);
    gemm128<1><<<dim3(M_/128, 1), blk>>>(x, Wg, bg, g, M_, C_, D_);

    // alpha/beta scalars
    ab_kernel<<<M_/8, blk>>>(x, Wa, ba, Wb, bb, a, b);

    // chunked sequential recurrence (128 CTAs, 1 barrier per 4 steps)
    recurrence4<<<dim3(GROUPS, B_), blk>>>(q, k, v, a, b, op);

    // group-sum + gate
    combine_kernel<<<(M_*C_/4)/256, blk>>>(op, g, o);

    // output projection (M=65536, N=1024, K=128)
    gemm128<0><<<dim3(M_/128, D_/128), blk>>>(o, Wo, bo, out, M_, D_, C_);
}

// round 4
// speedup vs baseline: 2.0605x; 1.4779x over previous
#include <cuda_runtime.h>
#include <cuda_bf16.h>
#include <cstdint>

#define B_ 16
#define T_ 4096
#define D_ 1024
#define C_ 128
#define M_ (B_*T_)        // 65536 tokens
#define GROUPS 8          // row-groups for recurrence parallelism
#define LCH 4             // chunk length inside recurrence

typedef __nv_bfloat16 bf16;

// ---------------- scratch (static device globals; no allocation) -------------
__device__ float g_q[(size_t)M_*C_];
__device__ float g_k[(size_t)M_*C_];
__device__ float g_v[(size_t)M_*C_];
__device__ float g_g[(size_t)M_*C_];
__device__ float g_a[M_];
__device__ float g_b[M_];
__device__ float g_opart[(size_t)GROUPS*M_*C_];

__device__ bf16 g_xh[(size_t)M_*D_];
__device__ bf16 g_xl[(size_t)M_*D_];
__device__ bf16 g_oh[(size_t)M_*C_];
__device__ bf16 g_ol[(size_t)M_*C_];
__device__ bf16 g_wqh[C_*D_], g_wql[C_*D_];
__device__ bf16 g_wkh[C_*D_], g_wkl[C_*D_];
__device__ bf16 g_wvh[C_*D_], g_wvl[C_*D_];
__device__ bf16 g_wgh[C_*D_], g_wgl[C_*D_];
__device__ bf16 g_woh[D_*C_], g_wol[D_*C_];

__device__ __forceinline__ float sigmoidf_(float x) { return 1.0f / (1.0f + expf(-x)); }

// =============================================================================
// fp32 -> bf16 hi/lo split:  hi = bf16(x), lo = bf16(x - hi)
// =============================================================================
__global__ __launch_bounds__(256) void split_kernel(const float* __restrict__ in,
                                                    bf16* __restrict__ hi,
                                                    bf16* __restrict__ lo,
                                                    int n4)
{
    const int i = blockIdx.x * 256 + threadIdx.x;
    if (i >= n4) return;
    float4 x = *(const float4*)(in + (size_t)i * 4);
    bf16 h0 = __float2bfloat16_rn(x.x);
    bf16 h1 = __float2bfloat16_rn(x.y);
    bf16 h2 = __float2bfloat16_rn(x.z);
    bf16 h3 = __float2bfloat16_rn(x.w);
    bf16 l0 = __float2bfloat16_rn(x.x - __bfloat162float(h0));
    bf16 l1 = __float2bfloat16_rn(x.y - __bfloat162float(h1));
    bf16 l2 = __float2bfloat16_rn(x.z - __bfloat162float(h2));
    bf16 l3 = __float2bfloat16_rn(x.w - __bfloat162float(h3));
    __nv_bfloat162* H = (__nv_bfloat162*)(hi + (size_t)i * 4);
    __nv_bfloat162* L = (__nv_bfloat162*)(lo + (size_t)i * 4);
    H[0] = __nv_bfloat162(h0, h1); H[1] = __nv_bfloat162(h2, h3);
    L[0] = __nv_bfloat162(l0, l1); L[1] = __nv_bfloat162(l2, l3);
}

// =============================================================================
// Tensor-core NT GEMM core: C[m][n] = sum_p sum_k Ap[m,k]*Bp[n,k]
// Parts: (A0,B0),(A1,B1),(A2,B2) — caller passes (Ah,Bh),(Ah,Bl),(Al,Bh).
// CTA tile 128x128, KT=32 bf16 per iter, 8 warps (2 M x 4 N) of 64x32,
// HMMA m16n8k16, fp32 accum, double-buffered swizzled smem, 1 barrier/iter.
// =============================================================================
__device__ __forceinline__ void ldsm4(uint32_t& r0, uint32_t& r1,
                                      uint32_t& r2, uint32_t& r3, uint32_t a)
{
    asm volatile("ldmatrix.sync.aligned.m8n8.x4.shared.b16 {%0,%1,%2,%3}, [%4];"
                 : "=r"(r0), "=r"(r1), "=r"(r2), "=r"(r3) : "r"(a));
}

__device__ __forceinline__ void mma16816(float c[4], const uint32_t a[4], const uint32_t b[2])
{
    asm volatile("mma.sync.aligned.m16n8k16.row.col.f32.bf16.bf16.f32 "
                 "{%0,%1,%2,%3}, {%4,%5,%6,%7}, {%8,%9}, {%0,%1,%2,%3};"
                 : "+f"(c[0]), "+f"(c[1]), "+f"(c[2]), "+f"(c[3])
                 : "r"(a[0]), "r"(a[1]), "r"(a[2]), "r"(a[3]), "r"(b[0]), "r"(b[1]));
}

template<int KDIM>
__device__ __forceinline__ void mma_loop(const bf16* __restrict__ A0,
                                         const bf16* __restrict__ A1,
                                         const bf16* __restrict__ A2,
                                         const bf16* __restrict__ B0,
                                         const bf16* __restrict__ B1,
                                         const bf16* __restrict__ B2,
                                         int m0, uint4* sA, uint4* sB,
                                         float acc[4][4][4])
{
    constexpr int KIT = KDIM / 32;
    constexpr int TOT = 3 * KIT;
    const int tid  = threadIdx.x;
    const int lane = tid & 31, warp = tid >> 5;
    const int wm = warp & 1, wn = warp >> 1;

    // loader slots: slot = s*256+tid -> row = slot>>2 (0..127), u16 = slot&3
    const int r0_ = tid >> 2,        u_ = tid & 3;
    const int r1_ = 64 + (tid >> 2);
    const int st0 = r0_ * 4 + (u_ ^ ((r0_ >> 1) & 3));
    const int st1 = r1_ * 4 + (u_ ^ ((r1_ >> 1) & 3));

    const uint32_t saB = (uint32_t)__cvta_generic_to_shared(sA);
    const uint32_t sbB = (uint32_t)__cvta_generic_to_shared(sB);

    uint4 ra0, ra1, rb0, rb1;

    // prologue
    {
        const bf16* Ap = A0; const bf16* Bp = B0;
        ra0 = *(const uint4*)(Ap + (size_t)(m0 + r0_) * KDIM + u_ * 8);
        ra1 = *(const uint4*)(Ap + (size_t)(m0 + r1_) * KDIM + u_ * 8);
        rb0 = *(const uint4*)(Bp + (size_t)r0_ * KDIM + u_ * 8);
        rb1 = *(const uint4*)(Bp + (size_t)r1_ * KDIM + u_ * 8);
    }

#pragma unroll 1
    for (int it = 0; it < TOT; ++it) {
        const int buf = it & 1;
        sA[buf * 512 + st0] = ra0; sA[buf * 512 + st1] = ra1;
        sB[buf * 512 + st0] = rb0; sB[buf * 512 + st1] = rb1;
        __syncthreads();

        if (it + 1 < TOT) {
            const int nit = it + 1;
            const int p = nit / KIT;
            const int kk = (nit - p * KIT) * 32;
            const bf16* Ap = (p == 0) ? A0 : (p == 1) ? A1 : A2;
            const bf16* Bp = (p == 0) ? B0 : (p == 1) ? B1 : B2;
            ra0 = *(const uint4*)(Ap + (size_t)(m0 + r0_) * KDIM + kk + u_ * 8);
            ra1 = *(const uint4*)(Ap + (size_t)(m0 + r1_) * KDIM + kk + u_ * 8);
            rb0 = *(const uint4*)(Bp + (size_t)r0_ * KDIM + kk + u_ * 8);
            rb1 = *(const uint4*)(Bp + (size_t)r1_ * KDIM + kk + u_ * 8);
        }

        const uint32_t aBase = saB + buf * 8192;
        const uint32_t bBase = sbB + buf * 8192;
#pragma unroll
        for (int ks = 0; ks < 2; ++ks) {
            uint32_t af[4][4], bfr[4][2];
#pragma unroll
            for (int mt = 0; mt < 4; ++mt) {
                const int row = wm * 64 + mt * 16 + (lane & 15);
                const int u = ks * 2 + (lane >> 4);
                ldsm4(af[mt][0], af[mt][1], af[mt][2], af[mt][3],
                      aBase + (uint32_t)((row * 4 + (u ^ ((row >> 1) & 3))) * 16));
            }
#pragma unroll
            for (int j = 0; j < 2; ++j) {
                const int gq = lane >> 3;
                const int n = wn * 32 + j * 16 + ((gq >> 1) << 3) + (lane & 7);
                const int u = ks * 2 + (gq & 1);
                uint32_t t0, t1, t2, t3;
                ldsm4(t0, t1, t2, t3,
                      bBase + (uint32_t)((n * 4 + (u ^ ((n >> 1) & 3))) * 16));
                bfr[j*2][0] = t0; bfr[j*2][1] = t1;
                bfr[j*2+1][0] = t2; bfr[j*2+1][1] = t3;
            }
#pragma unroll
            for (int mt = 0; mt < 4; ++mt)
#pragma unroll
                for (int nt = 0; nt < 4; ++nt)
                    mma16816(acc[mt][nt], af[mt], bfr[nt]);
        }
        // one barrier per iter: stores to buf^1 by fast warps are safe while
        // slow warps compute buf; re-store of buf is gated by the next barrier.
    }
}

// =============================================================================
// Fused 4-projection GEMM: blockIdx.x = {q,k,v,g}, blockIdx.y = m-tile.
// Epilogue: +bias, proj k -> row L2 normalize, proj g -> sigmoid. fp32 out.
// =============================================================================
__global__ __launch_bounds__(256, 2) void proj_gemm(
    const bf16* __restrict__ xh, const bf16* __restrict__ xl,
    const bf16* wqh, const bf16* wql, const bf16* wkh, const bf16* wkl,
    const bf16* wvh, const bf16* wvl, const bf16* wgh, const bf16* wgl,
    const float* bq, const float* bk, const float* bv, const float* bg,
    float* outq, float* outk, float* outv, float* outg)
{
    __shared__ uint4 sA[1024];
    __shared__ uint4 sB[1024];
    __shared__ float snorm[4][128];

    const int proj = blockIdx.x;
    const int m0 = blockIdx.y * 128;
    const bf16 *Bh, *Bl; const float* bias; float* C;
    if      (proj == 0) { Bh = wqh; Bl = wql; bias = bq; C = outq; }
    else if (proj == 1) { Bh = wkh; Bl = wkl; bias = bk; C = outk; }
    else if (proj == 2) { Bh = wvh; Bl = wvl; bias = bv; C = outv; }
    else                { Bh = wgh; Bl = wgl; bias = bg; C = outg; }

    float acc[4][4][4];
#pragma unroll
    for (int mt = 0; mt < 4; ++mt)
#pragma unroll
        for (int nt = 0; nt < 4; ++nt)
#pragma unroll
            for (int c = 0; c < 4; ++c) acc[mt][nt][c] = 0.0f;

    mma_loop<D_>(xh, xh, xl, Bh, Bl, Bh, m0, sA, sB, acc);

    const int lane = threadIdx.x & 31, warp = threadIdx.x >> 5;
    const int wm = warp & 1, wn = warp >> 1;

    // bias
#pragma unroll
    for (int nt = 0; nt < 4; ++nt) {
        const int col = wn * 32 + nt * 8 + (lane & 3) * 2;
        const float b0 = bias[col], b1 = bias[col + 1];
#pragma unroll
        for (int mt = 0; mt < 4; ++mt) {
            acc[mt][nt][0] += b0; acc[mt][nt][1] += b1;
            acc[mt][nt][2] += b0; acc[mt][nt][3] += b1;
        }
    }

    if (proj == 3) {
#pragma unroll
        for (int mt = 0; mt < 4; ++mt)
#pragma unroll
            for (int nt = 0; nt < 4; ++nt)
#pragma unroll
                for (int c = 0; c < 4; ++c)
                    acc[mt][nt][c] = sigmoidf_(acc[mt][nt][c]);
    }

    if (proj == 1) {
        // row L2 norm across the CTA's full 128 cols (4 n-warps)
#pragma unroll
        for (int mt = 0; mt < 4; ++mt)
#pragma unroll
            for (int h = 0; h < 2; ++h) {
                float ss = 0.0f;
#pragma unroll
                for (int nt = 0; nt < 4; ++nt) {
                    ss += acc[mt][nt][2*h] * acc[mt][nt][2*h];
                    ss += acc[mt][nt][2*h+1] * acc[mt][nt][2*h+1];
                }
                ss += __shfl_xor_sync(0xffffffffu, ss, 1);
                ss += __shfl_xor_sync(0xffffffffu, ss, 2);
                if ((lane & 3) == 0)
                    snorm[wn][wm*64 + mt*16 + h*8 + (lane >> 2)] = ss;
            }
        __syncthreads();
#pragma unroll
        for (int mt = 0; mt < 4; ++mt)
#pragma unroll
            for (int h = 0; h < 2; ++h) {
                const int row = wm*64 + mt*16 + h*8 + (lane >> 2);
                const float s = snorm[0][row] + snorm[1][row] + snorm[2][row] + snorm[3][row];
                const float inv = 1.0f / fmaxf(sqrtf(s), 1e-12f);
#pragma unroll
                for (int nt = 0; nt < 4; ++nt) {
                    acc[mt][nt][2*h]   *= inv;
                    acc[mt][nt][2*h+1] *= inv;
                }
            }
    }

    // store (ldc = 128)
#pragma unroll
    for (int mt = 0; mt < 4; ++mt) {
        const int r = m0 + wm*64 + mt*16 + (lane >> 2);
#pragma unroll
        for (int nt = 0; nt < 4; ++nt) {
            const int col = wn*32 + nt*8 + (lane & 3)*2;
            *(float2*)(C + (size_t)r * C_ + col)       = make_float2(acc[mt][nt][0], acc[mt][nt][1]);
            *(float2*)(C + (size_t)(r+8) * C_ + col)   = make_float2(acc[mt][nt][2], acc[mt][nt][3]);
        }
    }
}

// =============================================================================
// Output GEMM: out[m][n] = o[m]·Wo[n] + bo[n], K=128, N=1024.
// =============================================================================
__global__ __launch_bounds__(256, 2) void out_gemm(
    const bf16* __restrict__ oh, const bf16* __restrict__ ol,
    const bf16* __restrict__ woh, const bf16* __restrict__ wol,
    const float* __restrict__ bo, float* __restrict__ out)
{
    __shared__ uint4 sA[1024];
    __shared__ uint4 sB[1024];

    const int n0 = blockIdx.x * 128;
    const int m0 = blockIdx.y * 128;
    const bf16* Bh = woh + (size_t)n0 * C_;
    const bf16* Bl = wol + (size_t)n0 * C_;

    float acc[4][4][4];
#pragma unroll
    for (int mt = 0; mt < 4; ++mt)
#pragma unroll
        for (int nt = 0; nt < 4; ++nt)
#pragma unroll
            for (int c = 0; c < 4; ++c) acc[mt][nt][c] = 0.0f;

    mma_loop<C_>(oh, oh, ol, Bh, Bl, Bh, m0, sA, sB, acc);

    const int lane = threadIdx.x & 31, warp = threadIdx.x >> 5;
    const int wm = warp & 1, wn = warp >> 1;

#pragma unroll
    for (int mt = 0; mt < 4; ++mt) {
        const int r = m0 + wm*64 + mt*16 + (lane >> 2);
#pragma unroll
        for (int nt = 0; nt < 4; ++nt) {
            const int col = n0 + wn*32 + nt*8 + (lane & 3)*2;
            const float b0 = bo[col], b1 = bo[col + 1];
            *(float2*)(out + (size_t)r * D_ + col)
                = make_float2(acc[mt][nt][0] + b0, acc[mt][nt][1] + b1);
            *(float2*)(out + (size_t)(r+8) * D_ + col)
                = make_float2(acc[mt][nt][2] + b0, acc[mt][nt][3] + b1);
        }
    }
}

// =============================================================================
// alpha/beta: per-token dot over D with Wa/Wb, + bias, sigmoid. (fp32)
// =============================================================================
__global__ __launch_bounds__(256) void ab_kernel(const float* __restrict__ x,
                                                 const float* __restrict__ Wa,
                                                 const float* __restrict__ ba,
                                                 const float* __restrict__ Wb,
                                                 const float* __restrict__ bb,
                                                 float* __restrict__ a_out,
                                                 float* __restrict__ b_out)
{
    __shared__ __align__(16) float sWa[D_];
    __shared__ __align__(16) float sWb[D_];
    const int tid = threadIdx.x;
    for (int i = tid; i < D_; i += 256) { sWa[i] = Wa[i]; sWb[i] = Wb[i]; }
    __syncthreads();

    const int warp = tid >> 5, lane = tid & 31;
    const int tok  = blockIdx.x * 8 + warp;
    const float* xr = x + (size_t)tok * D_;

    float da = 0.0f, db = 0.0f;
#pragma unroll
    for (int j = 0; j < 8; ++j) {
        float4 xv = *(const float4*)(xr  + j*128 + lane*4);
        float4 wa = *(const float4*)(sWa + j*128 + lane*4);
        float4 wb = *(const float4*)(sWb + j*128 + lane*4);
        da += xv.x*wa.x + xv.y*wa.y + xv.z*wa.z + xv.w*wa.w;
        db += xv.x*wb.x + xv.y*wb.y + xv.z*wb.z + xv.w*wb.w;
    }
#pragma unroll
    for (int off = 16; off > 0; off >>= 1) {
        da += __shfl_xor_sync(0xffffffffu, da, off);
        db += __shfl_xor_sync(0xffffffffu, db, off);
    }
    if (lane == 0) {
        a_out[tok] = sigmoidf_(da + ba[0]);
        b_out[tok] = sigmoidf_(db + bb[0]);
    }
}

// =============================================================================
// Chunked (L=4) gated delta-rule recurrence (unchanged from round 3).
// =============================================================================
struct ChunkRegs {
    float k[LCH][8];
    float q[LCH], v[LCH], a[LCH], b[LCH];
};

__device__ __forceinline__ float red16(float x) {
    x += __shfl_xor_sync(0xffffffffu, x, 1);
    x += __shfl_xor_sync(0xffffffffu, x, 2);
    x += __shfl_xor_sync(0xffffffffu, x, 4);
    x += __shfl_xor_sync(0xffffffffu, x, 8);
    return x;
}

__device__ __forceinline__ void load_chunk(int tcN,
                                           const float* __restrict__ kg,
                                           const float* __restrict__ qg,
                                           const float* __restrict__ vg,
                                           const float* __restrict__ ag,
                                           const float* __restrict__ bg,
                                           int i, int jb, ChunkRegs& R)
{
#pragma unroll
    for (int t4 = 0; t4 < LCH; ++t4) {
        const size_t off = ((size_t)tcN*LCH + t4) * C_;
        float4 x0 = *(const float4*)(kg + off + jb);
        float4 x1 = *(const float4*)(kg + off + jb + 4);
        R.k[t4][0]=x0.x; R.k[t4][1]=x0.y; R.k[t4][2]=x0.z; R.k[t4][3]=x0.w;
        R.k[t4][4]=x1.x; R.k[t4][5]=x1.y; R.k[t4][6]=x1.z; R.k[t4][7]=x1.w;
        R.q[t4] = qg[off + i];
        R.v[t4] = vg[off + i];
    }
    float4 a4 = *(const float4*)(ag + tcN*LCH);
    float4 b4 = *(const float4*)(bg + tcN*LCH);
    R.a[0]=a4.x; R.a[1]=a4.y; R.a[2]=a4.z; R.a[3]=a4.w;
    R.b[0]=b4.x; R.b[1]=b4.y; R.b[2]=b4.z; R.b[3]=b4.w;
}

__device__ __forceinline__ void chunk_body(int tc, int buf, bool pf,
                                           float S[8], ChunkRegs& cur, ChunkRegs& nxt,
                                           const float* __restrict__ kg,
                                           const float* __restrict__ qg,
                                           const float* __restrict__ vg,
                                           const float* __restrict__ ag,
                                           const float* __restrict__ bg,
                                           float* __restrict__ op,
                                           int i, int jb, int warp, int lane, int tid,
                                           float (*osh)[LCH][8][C_])
{
    float m[LCH];
#pragma unroll
    for (int t4 = 0; t4 < LCH; ++t4) {
        float s = 0.0f;
#pragma unroll
        for (int jj = 0; jj < 8; ++jj) s += S[jj] * cur.k[t4][jj];
        m[t4] = s;
    }
    float G01=0, G02=0, G03=0, G12=0, G13=0, G23=0;
#pragma unroll
    for (int jj = 0; jj < 8; ++jj) {
        const float k0 = cur.k[0][jj], k1 = cur.k[1][jj];
        const float k2 = cur.k[2][jj], k3 = cur.k[3][jj];
        G01 += k0*k1; G02 += k0*k2; G03 += k0*k3;
        G12 += k1*k2; G13 += k1*k3; G23 += k2*k3;
    }

    if (pf) load_chunk(tc + 1, kg, qg, vg, ag, bg, i, jb, nxt);

    m[0]=red16(m[0]); m[1]=red16(m[1]); m[2]=red16(m[2]); m[3]=red16(m[3]);
    G01=red16(G01); G02=red16(G02); G03=red16(G03);
    G12=red16(G12); G13=red16(G13); G23=red16(G23);

    const float a0=cur.a[0], a1=cur.a[1], a2=cur.a[2], a3=cur.a[3];
    const float u0 = m[0];
    const float c0 = cur.b[0] * (cur.v[0] - a0*u0);
    const float u1 = a0*m[1] + c0*G01;
    const float c1 = cur.b[1] * (cur.v[1] - a1*u1);
    const float a01 = a0*a1;
    const float u2 = a01*m[2] + a1*c0*G02 + c1*G12;
    const float c2 = cur.b[2] * (cur.v[2] - a2*u2);
    const float u3 = a01*a2*m[3] + a1*a2*c0*G03 + a2*c1*G13 + c2*G23;
    const float c3 = cur.b[3] * (cur.v[3] - a3*u3);
    const float cc[LCH] = {c0, c1, c2, c3};

#pragma unroll
    for (int t4 = 0; t4 < LCH; ++t4) {
        float po[8];
#pragma unroll
        for (int jj = 0; jj < 8; ++jj) {
            S[jj] = cur.a[t4] * S[jj] + cc[t4] * cur.k[t4][jj];
            po[jj] = cur.q[t4] * S[jj];
        }
#pragma unroll
        for (int jj = 0; jj < 8; ++jj)
            po[jj] += __shfl_xor_sync(0xffffffffu, po[jj], 16);
        if (lane < 16) {
            float4* dst = (float4*)&osh[buf][t4][warp][(lane & 15) * 8];
            dst[0] = make_float4(po[0], po[1], po[2], po[3]);
            dst[1] = make_float4(po[4], po[5], po[6], po[7]);
        }
    }
    __syncthreads();

#pragma unroll
    for (int ss = 0; ss < 2; ++ss) {
        const int slot = tid + ss * 256;
        const int t4 = slot >> 7, j = slot & 127;
        float oo = 0.0f;
#pragma unroll
        for (int w = 0; w < 8; ++w) oo += osh[buf][t4][w][j];
        op[((size_t)tc*LCH + t4) * C_ + j] = oo;
    }
}

__global__ __launch_bounds__(256) void recurrence4(const float* __restrict__ q,
                                                   const float* __restrict__ k,
                                                   const float* __restrict__ v,
                                                   const float* __restrict__ al,
                                                   const float* __restrict__ be,
                                                   float* __restrict__ opart)
{
    const int g   = blockIdx.x;
    const int bb  = blockIdx.y;
    const int tid = threadIdx.x;
    const int warp = tid >> 5, lane = tid & 31;
    const int rl = warp * 2 + (lane >> 4);
    const int i  = g * 16 + rl;
    const int jb = (lane & 15) * 8;

    __shared__ __align__(16) float osh[2][LCH][8][C_];

    const size_t bbase = (size_t)bb * T_ * C_;
    const size_t sbase = (size_t)bb * T_;
    const float* kg = k + bbase;
    const float* qg = q + bbase;
    const float* vg = v + bbase;
    const float* ag = al + sbase;
    const float* bg = be + sbase;
    float* op = opart + (size_t)g * M_ * C_ + bbase;

    float S[8];
#pragma unroll
    for (int jj = 0; jj < 8; ++jj) S[jj] = 0.0f;

    ChunkRegs RA, RB;
    load_chunk(0, kg, qg, vg, ag, bg, i, jb, RA);

    const int NC = T_ / LCH;
#pragma unroll 1
    for (int tc = 0; tc < NC; tc += 2) {
        chunk_body(tc,   0, true,          S, RA, RB, kg, qg, vg, ag, bg, op, i, jb, warp, lane, tid, osh);
        chunk_body(tc+1, 1, (tc+2) < NC,   S, RB, RA, kg, qg, vg, ag, bg, op, i, jb, warp, lane, tid, osh);
    }
}

// =============================================================================
// combine: o = (sum over groups of opart) * gate -> bf16 hi/lo split
// =============================================================================
__global__ __launch_bounds__(256) void combine_split(const float* __restrict__ opart,
                                                     const float* __restrict__ gate,
                                                     bf16* __restrict__ oh,
                                                     bf16* __restrict__ ol)
{
    const size_t idx = ((size_t)blockIdx.x * 256 + threadIdx.x) * 4;
    float4 s = make_float4(0.f, 0.f, 0.f, 0.f);
#pragma unroll
    for (int g = 0; g < GROUPS; ++g) {
        float4 p = *(const float4*)(opart + (size_t)g * M_ * C_ + idx);
        s.x += p.x; s.y += p.y; s.z += p.z; s.w += p.w;
    }
    float4 gt = *(const float4*)(gate + idx);
    s.x *= gt.x; s.y *= gt.y; s.z *= gt.z; s.w *= gt.w;

    bf16 h0 = __float2bfloat16_rn(s.x);
    bf16 h1 = __float2bfloat16_rn(s.y);
    bf16 h2 = __float2bfloat16_rn(s.z);
    bf16 h3 = __float2bfloat16_rn(s.w);
    bf16 l0 = __float2bfloat16_rn(s.x - __bfloat162float(h0));
    bf16 l1 = __float2bfloat16_rn(s.y - __bfloat162float(h1));
    bf16 l2 = __float2bfloat16_rn(s.z - __bfloat162float(h2));
    bf16 l3 = __float2bfloat16_rn(s.w - __bfloat162float(h3));
    __nv_bfloat162* H = (__nv_bfloat162*)(oh + idx);
    __nv_bfloat162* L = (__nv_bfloat162*)(ol + idx);
    H[0] = __nv_bfloat162(h0, h1); H[1] = __nv_bfloat162(h2, h3);
    L[0] = __nv_bfloat162(l0, l1); L[1] = __nv_bfloat162(l2, l3);
}

// =============================================================================
extern "C" void kernel_launch(void* const* d_in, const int* in_sizes, int n_in,
                              void* d_out, int out_size)
{
    const float* x  = (const float*)d_in[0];
    const float* Wq = (const float*)d_in[1];
    const float* bq = (const float*)d_in[2];
    const float* Wk = (const float*)d_in[3];
    const float* bk = (const float*)d_in[4];
    const float* Wv = (const float*)d_in[5];
    const float* bv = (const float*)d_in[6];
    const float* Wa = (const float*)d_in[7];
    const float* ba = (const float*)d_in[8];
    const float* Wb = (const float*)d_in[9];
    const float* bb = (const float*)d_in[10];
    const float* Wg = (const float*)d_in[11];
    const float* bg = (const float*)d_in[12];
    const float* Wo = (const float*)d_in[13];
    const float* bo = (const float*)d_in[14];
    float* out = (float*)d_out;

    float *q, *k, *v, *g, *a, *b, *op;
    bf16 *xh, *xl, *oh, *ol;
    bf16 *wqh, *wql, *wkh, *wkl, *wvh, *wvl, *wgh, *wgl, *woh, *wol;
    cudaGetSymbolAddress((void**)&q,  g_q);
    cudaGetSymbolAddress((void**)&k,  g_k);
    cudaGetSymbolAddress((void**)&v,  g_v);
    cudaGetSymbolAddress((void**)&g,  g_g);
    cudaGetSymbolAddress((void**)&a,  g_a);
    cudaGetSymbolAddress((void**)&b,  g_b);
    cudaGetSymbolAddress((void**)&op, g_opart);
    cudaGetSymbolAddress((void**)&xh, g_xh);
    cudaGetSymbolAddress((void**)&xl, g_xl);
    cudaGetSymbolAddress((void**)&oh, g_oh);
    cudaGetSymbolAddress((void**)&ol, g_ol);
    cudaGetSymbolAddress((void**)&wqh, g_wqh); cudaGetSymbolAddress((void**)&wql, g_wql);
    cudaGetSymbolAddress((void**)&wkh, g_wkh); cudaGetSymbolAddress((void**)&wkl, g_wkl);
    cudaGetSymbolAddress((void**)&wvh, g_wvh); cudaGetSymbolAddress((void**)&wvl, g_wvl);
    cudaGetSymbolAddress((void**)&wgh, g_wgh); cudaGetSymbolAddress((void**)&wgl, g_wgl);
    cudaGetSymbolAddress((void**)&woh, g_woh); cudaGetSymbolAddress((void**)&wol, g_wol);

    const dim3 blk(256);

    // bf16 hi/lo splits
    split_kernel<<<(M_*D_/4 + 255)/256, blk>>>(x, xh, xl, M_*D_/4);
    split_kernel<<<(C_*D_/4 + 255)/256, blk>>>(Wq, wqh, wql, C_*D_/4);
    split_kernel<<<(C_*D_/4 + 255)/256, blk>>>(Wk, wkh, wkl, C_*D_/4);
    split_kernel<<<(C_*D_/4 + 255)/256, blk>>>(Wv, wvh, wvl, C_*D_/4);
    split_kernel<<<(C_*D_/4 + 255)/256, blk>>>(Wg, wgh, wgl, C_*D_/4);
    split_kernel<<<(D_*C_/4 + 255)/256, blk>>>(Wo, woh, wol, D_*C_/4);

    // alpha/beta (exact fp32)
    ab_kernel<<<M_/8, blk>>>(x, Wa, ba, Wb, bb, a, b);

    // fused 4-projection tensor-core GEMM (k-norm + gate-sigmoid in epilogue)
    proj_gemm<<<dim3(4, M_/128), blk>>>(xh, xl,
                                        wqh, wql, wkh, wkl, wvh, wvl, wgh, wgl,
                                        bq, bk, bv, bg, q, k, v, g);

    // chunked sequential recurrence (128 CTAs)
    recurrence4<<<dim3(GROUPS, B_), blk>>>(q, k, v, a, b, op);

    // group-sum + gate -> bf16 split
    combine_split<<<(M_*C_/4)/256, blk>>>(op, g, oh, ol);

    // output projection (tensor cores)
    out_gemm<<<dim3(D_/128, M_/128), blk>>>(oh, ol, woh, wol, bo, out);
}

// round 5
// speedup vs baseline: 2.1008x; 1.0195x over previous
#include <cuda_runtime.h>
#include <cuda_bf16.h>
#include <cstdint>

#define B_ 16
#define T_ 4096
#define D_ 1024
#define C_ 128
#define M_ (B_*T_)        // 65536 tokens
#define GROUPS 16         // row-groups for recurrence parallelism (8 rows each)
#define LCH 4             // chunk length inside recurrence

typedef __nv_bfloat16 bf16;

// ---------------- scratch (static device globals; no allocation) -------------
__device__ float g_q[(size_t)M_*C_];
__device__ float g_k[(size_t)M_*C_];
__device__ float g_v[(size_t)M_*C_];
__device__ float g_g[(size_t)M_*C_];
__device__ float g_a[M_];
__device__ float g_b[M_];
__device__ float g_opart[(size_t)GROUPS*M_*C_];

__device__ bf16 g_xh[(size_t)M_*D_];
__device__ bf16 g_xl[(size_t)M_*D_];
__device__ bf16 g_oh[(size_t)M_*C_];
__device__ bf16 g_ol[(size_t)M_*C_];
__device__ bf16 g_wqh[C_*D_], g_wql[C_*D_];
__device__ bf16 g_wkh[C_*D_], g_wkl[C_*D_];
__device__ bf16 g_wvh[C_*D_], g_wvl[C_*D_];
__device__ bf16 g_wgh[C_*D_], g_wgl[C_*D_];
__device__ bf16 g_woh[D_*C_], g_wol[D_*C_];

__device__ __forceinline__ float sigmoidf_(float x) { return 1.0f / (1.0f + expf(-x)); }

// =============================================================================
// fp32 -> bf16 hi/lo split for TWO weight matrices (blockIdx.y selects).
// =============================================================================
__global__ __launch_bounds__(256) void split2_kernel(const float* __restrict__ in0,
                                                     bf16* __restrict__ h0, bf16* __restrict__ l0,
                                                     const float* __restrict__ in1,
                                                     bf16* __restrict__ h1, bf16* __restrict__ l1,
                                                     int n4)
{
    const float* in = blockIdx.y ? in1 : in0;
    bf16* hi = blockIdx.y ? h1 : h0;
    bf16* lo = blockIdx.y ? l1 : l0;
    const int i = blockIdx.x * 256 + threadIdx.x;
    if (i >= n4) return;
    float4 x = *(const float4*)(in + (size_t)i * 4);
    bf16 hh0 = __float2bfloat16_rn(x.x);
    bf16 hh1 = __float2bfloat16_rn(x.y);
    bf16 hh2 = __float2bfloat16_rn(x.z);
    bf16 hh3 = __float2bfloat16_rn(x.w);
    bf16 ll0 = __float2bfloat16_rn(x.x - __bfloat162float(hh0));
    bf16 ll1 = __float2bfloat16_rn(x.y - __bfloat162float(hh1));
    bf16 ll2 = __float2bfloat16_rn(x.z - __bfloat162float(hh2));
    bf16 ll3 = __float2bfloat16_rn(x.w - __bfloat162float(hh3));
    __nv_bfloat162* H = (__nv_bfloat162*)(hi + (size_t)i * 4);
    __nv_bfloat162* L = (__nv_bfloat162*)(lo + (size_t)i * 4);
    H[0] = __nv_bfloat162(hh0, hh1); H[1] = __nv_bfloat162(hh2, hh3);
    L[0] = __nv_bfloat162(ll0, ll1); L[1] = __nv_bfloat162(ll2, ll3);
}

// =============================================================================
// Fused: alpha/beta scalars (exact fp32) + x hi/lo bf16 split (one x pass).
// One warp per token, 8 tokens per CTA.
// =============================================================================
__global__ __launch_bounds__(256) void absplit_kernel(const float* __restrict__ x,
                                                      const float* __restrict__ Wa,
                                                      const float* __restrict__ ba,
                                                      const float* __restrict__ Wb,
                                                      const float* __restrict__ bb,
                                                      float* __restrict__ a_out,
                                                      float* __restrict__ b_out,
                                                      bf16* __restrict__ xh,
                                                      bf16* __restrict__ xl)
{
    __shared__ __align__(16) float sWa[D_];
    __shared__ __align__(16) float sWb[D_];
    const int tid = threadIdx.x;
    for (int i = tid; i < D_; i += 256) { sWa[i] = Wa[i]; sWb[i] = Wb[i]; }
    __syncthreads();

    const int warp = tid >> 5, lane = tid & 31;
    const int tok  = blockIdx.x * 8 + warp;
    const size_t base = (size_t)tok * D_;
    const float* xr = x + base;

    float da = 0.0f, db = 0.0f;
#pragma unroll
    for (int j = 0; j < 8; ++j) {
        const int off = j*128 + lane*4;
        float4 xv = *(const float4*)(xr  + off);
        float4 wa = *(const float4*)(sWa + off);
        float4 wb = *(const float4*)(sWb + off);
        da += xv.x*wa.x + xv.y*wa.y + xv.z*wa.z + xv.w*wa.w;
        db += xv.x*wb.x + xv.y*wb.y + xv.z*wb.z + xv.w*wb.w;

        bf16 h0 = __float2bfloat16_rn(xv.x);
        bf16 h1 = __float2bfloat16_rn(xv.y);
        bf16 h2 = __float2bfloat16_rn(xv.z);
        bf16 h3 = __float2bfloat16_rn(xv.w);
        bf16 l0 = __float2bfloat16_rn(xv.x - __bfloat162float(h0));
        bf16 l1 = __float2bfloat16_rn(xv.y - __bfloat162float(h1));
        bf16 l2 = __float2bfloat16_rn(xv.z - __bfloat162float(h2));
        bf16 l3 = __float2bfloat16_rn(xv.w - __bfloat162float(h3));
        __nv_bfloat162* H = (__nv_bfloat162*)(xh + base + off);
        __nv_bfloat162* L = (__nv_bfloat162*)(xl + base + off);
        H[0] = __nv_bfloat162(h0, h1); H[1] = __nv_bfloat162(h2, h3);
        L[0] = __nv_bfloat162(l0, l1); L[1] = __nv_bfloat162(l2, l3);
    }
#pragma unroll
    for (int off = 16; off > 0; off >>= 1) {
        da += __shfl_xor_sync(0xffffffffu, da, off);
        db += __shfl_xor_sync(0xffffffffu, db, off);
    }
    if (lane == 0) {
        a_out[tok] = sigmoidf_(da + ba[0]);
        b_out[tok] = sigmoidf_(db + bb[0]);
    }
}

// =============================================================================
// Tensor-core NT GEMM core (unchanged from round 4).
// =============================================================================
__device__ __forceinline__ void ldsm4(uint32_t& r0, uint32_t& r1,
                                      uint32_t& r2, uint32_t& r3, uint32_t a)
{
    asm volatile("ldmatrix.sync.aligned.m8n8.x4.shared.b16 {%0,%1,%2,%3}, [%4];"
                 : "=r"(r0), "=r"(r1), "=r"(r2), "=r"(r3) : "r"(a));
}

__device__ __forceinline__ void mma16816(float c[4], const uint32_t a[4], const uint32_t b[2])
{
    asm volatile("mma.sync.aligned.m16n8k16.row.col.f32.bf16.bf16.f32 "
                 "{%0,%1,%2,%3}, {%4,%5,%6,%7}, {%8,%9}, {%0,%1,%2,%3};"
                 : "+f"(c[0]), "+f"(c[1]), "+f"(c[2]), "+f"(c[3])
                 : "r"(a[0]), "r"(a[1]), "r"(a[2]), "r"(a[3]), "r"(b[0]), "r"(b[1]));
}

template<int KDIM>
__device__ __forceinline__ void mma_loop(const bf16* __restrict__ A0,
                                         const bf16* __restrict__ A1,
                                         const bf16* __restrict__ A2,
                                         const bf16* __restrict__ B0,
                                         const bf16* __restrict__ B1,
                                         const bf16* __restrict__ B2,
                                         int m0, uint4* sA, uint4* sB,
                                         float acc[4][4][4])
{
    constexpr int KIT = KDIM / 32;
    constexpr int TOT = 3 * KIT;
    const int tid  = threadIdx.x;
    const int lane = tid & 31, warp = tid >> 5;
    const int wm = warp & 1, wn = warp >> 1;

    const int r0_ = tid >> 2,        u_ = tid & 3;
    const int r1_ = 64 + (tid >> 2);
    const int st0 = r0_ * 4 + (u_ ^ ((r0_ >> 1) & 3));
    const int st1 = r1_ * 4 + (u_ ^ ((r1_ >> 1) & 3));

    const uint32_t saB = (uint32_t)__cvta_generic_to_shared(sA);
    const uint32_t sbB = (uint32_t)__cvta_generic_to_shared(sB);

    uint4 ra0, ra1, rb0, rb1;
    {
        ra0 = *(const uint4*)(A0 + (size_t)(m0 + r0_) * KDIM + u_ * 8);
        ra1 = *(const uint4*)(A0 + (size_t)(m0 + r1_) * KDIM + u_ * 8);
        rb0 = *(const uint4*)(B0 + (size_t)r0_ * KDIM + u_ * 8);
        rb1 = *(const uint4*)(B0 + (size_t)r1_ * KDIM + u_ * 8);
    }

#pragma unroll 1
    for (int it = 0; it < TOT; ++it) {
        const int buf = it & 1;
        sA[buf * 512 + st0] = ra0; sA[buf * 512 + st1] = ra1;
        sB[buf * 512 + st0] = rb0; sB[buf * 512 + st1] = rb1;
        __syncthreads();

        if (it + 1 < TOT) {
            const int nit = it + 1;
            const int p = nit / KIT;
            const int kk = (nit - p * KIT) * 32;
            const bf16* Ap = (p == 0) ? A0 : (p == 1) ? A1 : A2;
            const bf16* Bp = (p == 0) ? B0 : (p == 1) ? B1 : B2;
            ra0 = *(const uint4*)(Ap + (size_t)(m0 + r0_) * KDIM + kk + u_ * 8);
            ra1 = *(const uint4*)(Ap + (size_t)(m0 + r1_) * KDIM + kk + u_ * 8);
            rb0 = *(const uint4*)(Bp + (size_t)r0_ * KDIM + kk + u_ * 8);
            rb1 = *(const uint4*)(Bp + (size_t)r1_ * KDIM + kk + u_ * 8);
        }

        const uint32_t aBase = saB + buf * 8192;
        const uint32_t bBase = sbB + buf * 8192;
#pragma unroll
        for (int ks = 0; ks < 2; ++ks) {
            uint32_t af[4][4], bfr[4][2];
#pragma unroll
            for (int mt = 0; mt < 4; ++mt) {
                const int row = wm * 64 + mt * 16 + (lane & 15);
                const int u = ks * 2 + (lane >> 4);
                ldsm4(af[mt][0], af[mt][1], af[mt][2], af[mt][3],
                      aBase + (uint32_t)((row * 4 + (u ^ ((row >> 1) & 3))) * 16));
            }
#pragma unroll
            for (int j = 0; j < 2; ++j) {
                const int gq = lane >> 3;
                const int n = wn * 32 + j * 16 + ((gq >> 1) << 3) + (lane & 7);
                const int u = ks * 2 + (gq & 1);
                uint32_t t0, t1, t2, t3;
                ldsm4(t0, t1, t2, t3,
                      bBase + (uint32_t)((n * 4 + (u ^ ((n >> 1) & 3))) * 16));
                bfr[j*2][0] = t0; bfr[j*2][1] = t1;
                bfr[j*2+1][0] = t2; bfr[j*2+1][1] = t3;
            }
#pragma unroll
            for (int mt = 0; mt < 4; ++mt)
#pragma unroll
                for (int nt = 0; nt < 4; ++nt)
                    mma16816(acc[mt][nt], af[mt], bfr[nt]);
        }
    }
}

// =============================================================================
// Fused 4-projection GEMM (unchanged from round 4).
// =============================================================================
__global__ __launch_bounds__(256, 2) void proj_gemm(
    const bf16* __restrict__ xh, const bf16* __restrict__ xl,
    const bf16* wqh, const bf16* wql, const bf16* wkh, const bf16* wkl,
    const bf16* wvh, const bf16* wvl, const bf16* wgh, const bf16* wgl,
    const float* bq, const float* bk, const float* bv, const float* bg,
    float* outq, float* outk, float* outv, float* outg)
{
    __shared__ uint4 sA[1024];
    __shared__ uint4 sB[1024];
    __shared__ float snorm[4][128];

    const int proj = blockIdx.x;
    const int m0 = blockIdx.y * 128;
    const bf16 *Bh, *Bl; const float* bias; float* C;
    if      (proj == 0) { Bh = wqh; Bl = wql; bias = bq; C = outq; }
    else if (proj == 1) { Bh = wkh; Bl = wkl; bias = bk; C = outk; }
    else if (proj == 2) { Bh = wvh; Bl = wvl; bias = bv; C = outv; }
    else                { Bh = wgh; Bl = wgl; bias = bg; C = outg; }

    float acc[4][4][4];
#pragma unroll
    for (int mt = 0; mt < 4; ++mt)
#pragma unroll
        for (int nt = 0; nt < 4; ++nt)
#pragma unroll
            for (int c = 0; c < 4; ++c) acc[mt][nt][c] = 0.0f;

    mma_loop<D_>(xh, xh, xl, Bh, Bl, Bh, m0, sA, sB, acc);

    const int lane = threadIdx.x & 31, warp = threadIdx.x >> 5;
    const int wm = warp & 1, wn = warp >> 1;

#pragma unroll
    for (int nt = 0; nt < 4; ++nt) {
        const int col = wn * 32 + nt * 8 + (lane & 3) * 2;
        const float b0 = bias[col], b1 = bias[col + 1];
#pragma unroll
        for (int mt = 0; mt < 4; ++mt) {
            acc[mt][nt][0] += b0; acc[mt][nt][1] += b1;
            acc[mt][nt][2] += b0; acc[mt][nt][3] += b1;
        }
    }

    if (proj == 3) {
#pragma unroll
        for (int mt = 0; mt < 4; ++mt)
#pragma unroll
            for (int nt = 0; nt < 4; ++nt)
#pragma unroll
                for (int c = 0; c < 4; ++c)
                    acc[mt][nt][c] = sigmoidf_(acc[mt][nt][c]);
    }

    if (proj == 1) {
#pragma unroll
        for (int mt = 0; mt < 4; ++mt)
#pragma unroll
            for (int h = 0; h < 2; ++h) {
                float ss = 0.0f;
#pragma unroll
                for (int nt = 0; nt < 4; ++nt) {
                    ss += acc[mt][nt][2*h] * acc[mt][nt][2*h];
                    ss += acc[mt][nt][2*h+1] * acc[mt][nt][2*h+1];
                }
                ss += __shfl_xor_sync(0xffffffffu, ss, 1);
                ss += __shfl_xor_sync(0xffffffffu, ss, 2);
                if ((lane & 3) == 0)
                    snorm[wn][wm*64 + mt*16 + h*8 + (lane >> 2)] = ss;
            }
        __syncthreads();
#pragma unroll
        for (int mt = 0; mt < 4; ++mt)
#pragma unroll
            for (int h = 0; h < 2; ++h) {
                const int row = wm*64 + mt*16 + h*8 + (lane >> 2);
                const float s = snorm[0][row] + snorm[1][row] + snorm[2][row] + snorm[3][row];
                const float inv = 1.0f / fmaxf(sqrtf(s), 1e-12f);
#pragma unroll
                for (int nt = 0; nt < 4; ++nt) {
                    acc[mt][nt][2*h]   *= inv;
                    acc[mt][nt][2*h+1] *= inv;
                }
            }
    }

#pragma unroll
    for (int mt = 0; mt < 4; ++mt) {
        const int r = m0 + wm*64 + mt*16 + (lane >> 2);
#pragma unroll
        for (int nt = 0; nt < 4; ++nt) {
            const int col = wn*32 + nt*8 + (lane & 3)*2;
            *(float2*)(C + (size_t)r * C_ + col)       = make_float2(acc[mt][nt][0], acc[mt][nt][1]);
            *(float2*)(C + (size_t)(r+8) * C_ + col)   = make_float2(acc[mt][nt][2], acc[mt][nt][3]);
        }
    }
}

// =============================================================================
// Output GEMM (unchanged from round 4).
// =============================================================================
__global__ __launch_bounds__(256, 2) void out_gemm(
    const bf16* __restrict__ oh, const bf16* __restrict__ ol,
    const bf16* __restrict__ woh, const bf16* __restrict__ wol,
    const float* __restrict__ bo, float* __restrict__ out)
{
    __shared__ uint4 sA[1024];
    __shared__ uint4 sB[1024];

    const int n0 = blockIdx.x * 128;
    const int m0 = blockIdx.y * 128;
    const bf16* Bh = woh + (size_t)n0 * C_;
    const bf16* Bl = wol + (size_t)n0 * C_;

    float acc[4][4][4];
#pragma unroll
    for (int mt = 0; mt < 4; ++mt)
#pragma unroll
        for (int nt = 0; nt < 4; ++nt)
#pragma unroll
            for (int c = 0; c < 4; ++c) acc[mt][nt][c] = 0.0f;

    mma_loop<C_>(oh, oh, ol, Bh, Bl, Bh, m0, sA, sB, acc);

    const int lane = threadIdx.x & 31, warp = threadIdx.x >> 5;
    const int wm = warp & 1, wn = warp >> 1;

#pragma unroll
    for (int mt = 0; mt < 4; ++mt) {
        const int r = m0 + wm*64 + mt*16 + (lane >> 2);
#pragma unroll
        for (int nt = 0; nt < 4; ++nt) {
            const int col = n0 + wn*32 + nt*8 + (lane & 3)*2;
            const float b0 = bo[col], b1 = bo[col + 1];
            *(float2*)(out + (size_t)r * D_ + col)
                = make_float2(acc[mt][nt][0] + b0, acc[mt][nt][1] + b1);
            *(float2*)(out + (size_t)(r+8) * D_ + col)
                = make_float2(acc[mt][nt][2] + b0, acc[mt][nt][3] + b1);
        }
    }
}

// =============================================================================
// Chunked (L=4) gated delta-rule recurrence, GROUPS=16, ONE ROW PER WARP.
// Grid (16, 16) = 256 CTAs -> 2 CTAs/SM, 4 warps/SMSP.
// Warp w owns global state row i = g*8 + w; lane owns 4 columns (lane*4..+3).
// No cross-row shuffles in the hot per-step path; q/v loads are warp-uniform.
// =============================================================================
struct ChunkRegs {
    float k[LCH][4];
    float q[LCH], v[LCH], a[LCH], b[LCH];
};

__device__ __forceinline__ float red32(float x) {
    x += __shfl_xor_sync(0xffffffffu, x, 1);
    x += __shfl_xor_sync(0xffffffffu, x, 2);
    x += __shfl_xor_sync(0xffffffffu, x, 4);
    x += __shfl_xor_sync(0xffffffffu, x, 8);
    x += __shfl_xor_sync(0xffffffffu, x, 16);
    return x;
}

__device__ __forceinline__ void load_chunk(int tcN,
                                           const float* __restrict__ kg,
                                           const float* __restrict__ qg,
                                           const float* __restrict__ vg,
                                           const float* __restrict__ ag,
                                           const float* __restrict__ bg,
                                           int i, int jb, ChunkRegs& R)
{
#pragma unroll
    for (int t4 = 0; t4 < LCH; ++t4) {
        const size_t off = ((size_t)tcN*LCH + t4) * C_;
        float4 kx = *(const float4*)(kg + off + jb);
        R.k[t4][0]=kx.x; R.k[t4][1]=kx.y; R.k[t4][2]=kx.z; R.k[t4][3]=kx.w;
        R.q[t4] = qg[off + i];   // warp-uniform broadcast
        R.v[t4] = vg[off + i];
    }
    float4 a4 = *(const float4*)(ag + tcN*LCH);
    float4 b4 = *(const float4*)(bg + tcN*LCH);
    R.a[0]=a4.x; R.a[1]=a4.y; R.a[2]=a4.z; R.a[3]=a4.w;
    R.b[0]=b4.x; R.b[1]=b4.y; R.b[2]=b4.z; R.b[3]=b4.w;
}

__device__ __forceinline__ void chunk_body(int tc, int buf, bool pf,
                                           float S[4], ChunkRegs& cur, ChunkRegs& nxt,
                                           const float* __restrict__ kg,
                                           const float* __restrict__ qg,
                                           const float* __restrict__ vg,
                                           const float* __restrict__ ag,
                                           const float* __restrict__ bg,
                                           float* __restrict__ op,
                                           int i, int jb, int warp, int lane, int tid,
                                           float (*osh)[LCH][8][C_])
{
    // --- phase 1: per-row m partials + k-Gram partials (4 cols per lane) ---
    float m[LCH];
#pragma unroll
    for (int t4 = 0; t4 < LCH; ++t4) {
        float s = 0.0f;
#pragma unroll
        for (int jj = 0; jj < 4; ++jj) s += S[jj] * cur.k[t4][jj];
        m[t4] = s;
    }
    float G01=0, G02=0, G03=0, G12=0, G13=0, G23=0;
#pragma unroll
    for (int jj = 0; jj < 4; ++jj) {
        const float k0 = cur.k[0][jj], k1 = cur.k[1][jj];
        const float k2 = cur.k[2][jj], k3 = cur.k[3][jj];
        G01 += k0*k1; G02 += k0*k2; G03 += k0*k3;
        G12 += k1*k2; G13 += k1*k3; G23 += k2*k3;
    }

    // --- prefetch next chunk while reduces are in flight ---
    if (pf) load_chunk(tc + 1, kg, qg, vg, ag, bg, i, jb, nxt);

    // --- one batch of 10 independent full-warp reductions ---
    m[0]=red32(m[0]); m[1]=red32(m[1]); m[2]=red32(m[2]); m[3]=red32(m[3]);
    G01=red32(G01); G02=red32(G02); G03=red32(G03);
    G12=red32(G12); G13=red32(G13); G23=red32(G23);

    // --- phase 2: exact scalar recursion for c_tau ---
    const float a0=cur.a[0], a1=cur.a[1], a2=cur.a[2], a3=cur.a[3];
    const float u0 = m[0];
    const float c0 = cur.b[0] * (cur.v[0] - a0*u0);
    const float u1 = a0*m[1] + c0*G01;
    const float c1 = cur.b[1] * (cur.v[1] - a1*u1);
    const float a01 = a0*a1;
    const float u2 = a01*m[2] + a1*c0*G02 + c1*G12;
    const float c2 = cur.b[2] * (cur.v[2] - a2*u2);
    const float u3 = a01*a2*m[3] + a1*a2*c0*G03 + a2*c1*G13 + c2*G23;
    const float c3 = cur.b[3] * (cur.v[3] - a3*u3);
    const float cc[LCH] = {c0, c1, c2, c3};

    // --- phase 3: per-step register updates + o partials (NO shuffles) ---
#pragma unroll
    for (int t4 = 0; t4 < LCH; ++t4) {
        float po[4];
#pragma unroll
        for (int jj = 0; jj < 4; ++jj) {
            S[jj] = cur.a[t4] * S[jj] + cc[t4] * cur.k[t4][jj];
            po[jj] = cur.q[t4] * S[jj];
        }
        *(float4*)&osh[buf][t4][warp][lane * 4] = make_float4(po[0], po[1], po[2], po[3]);
    }
    __syncthreads();   // single barrier per chunk (osh double-buffered)

    // --- phase 4: cross-warp sum + global write (512 slots / 256 threads) ---
#pragma unroll
    for (int ss = 0; ss < 2; ++ss) {
        const int slot = tid + ss * 256;
        const int t4 = slot >> 7, j = slot & 127;
        float oo = 0.0f;
#pragma unroll
        for (int w = 0; w < 8; ++w) oo += osh[buf][t4][w][j];
        op[((size_t)tc*LCH + t4) * C_ + j] = oo;
    }
}

__global__ __launch_bounds__(256, 2) void recurrence4(const float* __restrict__ q,
                                                      const float* __restrict__ k,
                                                      const float* __restrict__ v,
                                                      const float* __restrict__ al,
                                                      const float* __restrict__ be,
                                                      float* __restrict__ opart)
{
    const int g   = blockIdx.x;   // row group 0..15 (8 rows each)
    const int bb  = blockIdx.y;   // batch 0..15
    const int tid = threadIdx.x;
    const int warp = tid >> 5, lane = tid & 31;
    const int i  = g * 8 + warp;  // global state row for this warp
    const int jb = lane * 4;      // first owned column

    __shared__ __align__(16) float osh[2][LCH][8][C_];

    const size_t bbase = (size_t)bb * T_ * C_;
    const size_t sbase = (size_t)bb * T_;
    const float* kg = k + bbase;
    const float* qg = q + bbase;
    const float* vg = v + bbase;
    const float* ag = al + sbase;
    const float* bg = be + sbase;
    float* op = opart + (size_t)g * M_ * C_ + bbase;

    float S[4];
#pragma unroll
    for (int jj = 0; jj < 4; ++jj) S[jj] = 0.0f;

    ChunkRegs RA, RB;
    load_chunk(0, kg, qg, vg, ag, bg, i, jb, RA);

    const int NC = T_ / LCH;
#pragma unroll 1
    for (int tc = 0; tc < NC; tc += 2) {
        chunk_body(tc,   0, true,          S, RA, RB, kg, qg, vg, ag, bg, op, i, jb, warp, lane, tid, osh);
        chunk_body(tc+1, 1, (tc+2) < NC,   S, RB, RA, kg, qg, vg, ag, bg, op, i, jb, warp, lane, tid, osh);
    }
}

// =============================================================================
// combine: o = (sum over groups of opart) * gate -> bf16 hi/lo split
// =============================================================================
__global__ __launch_bounds__(256) void combine_split(const float* __restrict__ opart,
                                                     const float* __restrict__ gate,
                                                     bf16* __restrict__ oh,
                                                     bf16* __restrict__ ol)
{
    const size_t idx = ((size_t)blockIdx.x * 256 + threadIdx.x) * 4;
    float4 s = make_float4(0.f, 0.f, 0.f, 0.f);
#pragma unroll
    for (int g = 0; g < GROUPS; ++g) {
        float4 p = *(const float4*)(opart + (size_t)g * M_ * C_ + idx);
        s.x += p.x; s.y += p.y; s.z += p.z; s.w += p.w;
    }
    float4 gt = *(const float4*)(gate + idx);
    s.x *= gt.x; s.y *= gt.y; s.z *= gt.z; s.w *= gt.w;

    bf16 h0 = __float2bfloat16_rn(s.x);
    bf16 h1 = __float2bfloat16_rn(s.y);
    bf16 h2 = __float2bfloat16_rn(s.z);
    bf16 h3 = __float2bfloat16_rn(s.w);
    bf16 l0 = __float2bfloat16_rn(s.x - __bfloat162float(h0));
    bf16 l1 = __float2bfloat16_rn(s.y - __bfloat162float(h1));
    bf16 l2 = __float2bfloat16_rn(s.z - __bfloat162float(h2));
    bf16 l3 = __float2bfloat16_rn(s.w - __bfloat162float(h3));
    __nv_bfloat162* H = (__nv_bfloat162*)(oh + idx);
    __nv_bfloat162* L = (__nv_bfloat162*)(ol + idx);
    H[0] = __nv_bfloat162(h0, h1); H[1] = __nv_bfloat162(h2, h3);
    L[0] = __nv_bfloat162(l0, l1); L[1] = __nv_bfloat162(l2, l3);
}

// =============================================================================
extern "C" void kernel_launch(void* const* d_in, const int* in_sizes, int n_in,
                              void* d_out, int out_size)
{
    const float* x  = (const float*)d_in[0];
    const float* Wq = (const float*)d_in[1];
    const float* bq = (const float*)d_in[2];
    const float* Wk = (const float*)d_in[3];
    const float* bk = (const float*)d_in[4];
    const float* Wv = (const float*)d_in[5];
    const float* bv = (const float*)d_in[6];
    const float* Wa = (const float*)d_in[7];
    const float* ba = (const float*)d_in[8];
    const float* Wb = (const float*)d_in[9];
    const float* bb = (const float*)d_in[10];
    const float* Wg = (const float*)d_in[11];
    const float* bg = (const float*)d_in[12];
    const float* Wo = (const float*)d_in[13];
    const float* bo = (const float*)d_in[14];
    float* out = (float*)d_out;

    float *q, *k, *v, *g, *a, *b, *op;
    bf16 *xh, *xl, *oh, *ol;
    bf16 *wqh, *wql, *wkh, *wkl, *wvh, *wvl, *wgh, *wgl, *woh, *wol;
    cudaGetSymbolAddress((void**)&q,  g_q);
    cudaGetSymbolAddress((void**)&k,  g_k);
    cudaGetSymbolAddress((void**)&v,  g_v);
    cudaGetSymbolAddress((void**)&g,  g_g);
    cudaGetSymbolAddress((void**)&a,  g_a);
    cudaGetSymbolAddress((void**)&b,  g_b);
    cudaGetSymbolAddress((void**)&op, g_opart);
    cudaGetSymbolAddress((void**)&xh, g_xh);
    cudaGetSymbolAddress((void**)&xl, g_xl);
    cudaGetSymbolAddress((void**)&oh, g_oh);
    cudaGetSymbolAddress((void**)&ol, g_ol);
    cudaGetSymbolAddress((void**)&wqh, g_wqh); cudaGetSymbolAddress((void**)&wql, g_wql);
    cudaGetSymbolAddress((void**)&wkh, g_wkh); cudaGetSymbolAddress((void**)&wkl, g_wkl);
    cudaGetSymbolAddress((void**)&wvh, g_wvh); cudaGetSymbolAddress((void**)&wvl, g_wvl);
    cudaGetSymbolAddress((void**)&wgh, g_wgh); cudaGetSymbolAddress((void**)&wgl, g_wgl);
    cudaGetSymbolAddress((void**)&woh, g_woh); cudaGetSymbolAddress((void**)&wol, g_wol);

    const dim3 blk(256);
    const int wn4 = C_*D_/4;   // 32768

    // weight hi/lo splits (3 launches)                         launch idx 0..2
    split2_kernel<<<dim3((wn4+255)/256, 2), blk>>>(Wq, wqh, wql, Wk, wkh, wkl, wn4);
    split2_kernel<<<dim3((wn4+255)/256, 2), blk>>>(Wv, wvh, wvl, Wg, wgh, wgl, wn4);
    split2_kernel<<<dim3((wn4+255)/256, 1), blk>>>(Wo, woh, wol, Wo, woh, wol, wn4);

    // fused alpha/beta + x split                               launch idx 3
    absplit_kernel<<<M_/8, blk>>>(x, Wa, ba, Wb, bb, a, b, xh, xl);

    // fused 4-projection tensor-core GEMM                      launch idx 4
    proj_gemm<<<dim3(4, M_/128), blk>>>(xh, xl,
                                        wqh, wql, wkh, wkl, wvh, wvl, wgh, wgl,
                                        bq, bk, bv, bg, q, k, v, g);

    // chunked sequential recurrence (256 CTAs)                 launch idx 5 (ncu -s 5)
    recurrence4<<<dim3(GROUPS, B_), blk>>>(q, k, v, a, b, op);

    // group-sum + gate -> bf16 split                           launch idx 6
    combine_split<<<(M_*C_/4)/256, blk>>>(op, g, oh, ol);

    // output projection (tensor cores)                         launch idx 7
    out_gemm<<<dim3(D_/128, M_/128), blk>>>(oh, ol, woh, wol, bo, out);
}

// round 7
// speedup vs baseline: 2.5207x; 1.1999x over previous
#include <cuda_runtime.h>
#include <cuda_bf16.h>
#include <cstdint>

#define B_ 16
#define T_ 4096
#define D_ 1024
#define C_ 128
#define M_ (B_*T_)        // 65536 tokens
#define GROUPS 16         // row-groups for recurrence parallelism (8 rows each)
#define LCH 4             // chunk length inside recurrence
#define NCH (T_/LCH)      // 1024 chunks per sequence

typedef __nv_bfloat16 bf16;

// ---------------- scratch (static device globals; no allocation) -------------
__device__ float g_q[(size_t)M_*C_];
__device__ float g_k[(size_t)M_*C_];
__device__ float g_v[(size_t)M_*C_];
__device__ float g_g[(size_t)M_*C_];
__device__ float g_a[M_];
__device__ float g_b[M_];
__device__ float g_opart[(size_t)GROUPS*M_*C_];
__device__ float g_gram[(size_t)B_*NCH*8];

__device__ bf16 g_xh[(size_t)M_*D_];
__device__ bf16 g_xl[(size_t)M_*D_];
__device__ bf16 g_oh[(size_t)M_*C_];
__device__ bf16 g_ol[(size_t)M_*C_];
__device__ bf16 g_wqh[C_*D_], g_wql[C_*D_];
__device__ bf16 g_wkh[C_*D_], g_wkl[C_*D_];
__device__ bf16 g_wvh[C_*D_], g_wvl[C_*D_];
__device__ bf16 g_wgh[C_*D_], g_wgl[C_*D_];
__device__ bf16 g_woh[D_*C_], g_wol[D_*C_];

__device__ __forceinline__ float sigmoidf_(float x) { return 1.0f / (1.0f + expf(-x)); }

// =============================================================================
// fused_prep: blocks [0, M_/8)            -> alpha/beta + x hi/lo split
//             blocks [M_/8, M_/8 + 640)   -> weight hi/lo splits (5 matrices)
// =============================================================================
__global__ __launch_bounds__(256) void fused_prep(
    const float* __restrict__ x,
    const float* __restrict__ Wa, const float* __restrict__ ba,
    const float* __restrict__ Wb, const float* __restrict__ bb,
    float* __restrict__ a_out, float* __restrict__ b_out,
    bf16* __restrict__ xh, bf16* __restrict__ xl,
    const float* Wq, const float* Wk, const float* Wv, const float* Wg, const float* Wo,
    bf16* wqh, bf16* wql, bf16* wkh, bf16* wkl, bf16* wvh, bf16* wvl,
    bf16* wgh, bf16* wgl, bf16* woh, bf16* wol)
{
    const int tid = threadIdx.x;
    constexpr int NAB = M_/8;   // 8192 absplit blocks

    if (blockIdx.x >= NAB) {
        // ---- weight split: 128 blocks per matrix, 5 matrices ----
        const int widx = blockIdx.x - NAB;
        const int mat  = widx >> 7;
        const float* in; bf16 *hi, *lo;
        if      (mat == 0) { in = Wq; hi = wqh; lo = wql; }
        else if (mat == 1) { in = Wk; hi = wkh; lo = wkl; }
        else if (mat == 2) { in = Wv; hi = wvh; lo = wvl; }
        else if (mat == 3) { in = Wg; hi = wgh; lo = wgl; }
        else               { in = Wo; hi = woh; lo = wol; }
        const int i = (widx & 127) * 256 + tid;   // < 32768 = C_*D_/4
        float4 xv = *(const float4*)(in + (size_t)i * 4);
        bf16 h0 = __float2bfloat16_rn(xv.x);
        bf16 h1 = __float2bfloat16_rn(xv.y);
        bf16 h2 = __float2bfloat16_rn(xv.z);
        bf16 h3 = __float2bfloat16_rn(xv.w);
        bf16 l0 = __float2bfloat16_rn(xv.x - __bfloat162float(h0));
        bf16 l1 = __float2bfloat16_rn(xv.y - __bfloat162float(h1));
        bf16 l2 = __float2bfloat16_rn(xv.z - __bfloat162float(h2));
        bf16 l3 = __float2bfloat16_rn(xv.w - __bfloat162float(h3));
        __nv_bfloat162* H = (__nv_bfloat162*)(hi + (size_t)i * 4);
        __nv_bfloat162* L = (__nv_bfloat162*)(lo + (size_t)i * 4);
        H[0] = __nv_bfloat162(h0, h1); H[1] = __nv_bfloat162(h2, h3);
        L[0] = __nv_bfloat162(l0, l1); L[1] = __nv_bfloat162(l2, l3);
        return;
    }

    // ---- absplit ----
    __shared__ __align__(16) float sWa[D_];
    __shared__ __align__(16) float sWb[D_];
    for (int i = tid; i < D_; i += 256) { sWa[i] = Wa[i]; sWb[i] = Wb[i]; }
    __syncthreads();

    const int warp = tid >> 5, lane = tid & 31;
    const int tok  = blockIdx.x * 8 + warp;
    const size_t base = (size_t)tok * D_;
    const float* xr = x + base;

    float da = 0.0f, db = 0.0f;
#pragma unroll
    for (int j = 0; j < 8; ++j) {
        const int off = j*128 + lane*4;
        float4 xv = *(const float4*)(xr  + off);
        float4 wa = *(const float4*)(sWa + off);
        float4 wb = *(const float4*)(sWb + off);
        da += xv.x*wa.x + xv.y*wa.y + xv.z*wa.z + xv.w*wa.w;
        db += xv.x*wb.x + xv.y*wb.y + xv.z*wb.z + xv.w*wb.w;

        bf16 h0 = __float2bfloat16_rn(xv.x);
        bf16 h1 = __float2bfloat16_rn(xv.y);
        bf16 h2 = __float2bfloat16_rn(xv.z);
        bf16 h3 = __float2bfloat16_rn(xv.w);
        bf16 l0 = __float2bfloat16_rn(xv.x - __bfloat162float(h0));
        bf16 l1 = __float2bfloat16_rn(xv.y - __bfloat162float(h1));
        bf16 l2 = __float2bfloat16_rn(xv.z - __bfloat162float(h2));
        bf16 l3 = __float2bfloat16_rn(xv.w - __bfloat162float(h3));
        __nv_bfloat162* H = (__nv_bfloat162*)(xh + base + off);
        __nv_bfloat162* L = (__nv_bfloat162*)(xl + base + off);
        H[0] = __nv_bfloat162(h0, h1); H[1] = __nv_bfloat162(h2, h3);
        L[0] = __nv_bfloat162(l0, l1); L[1] = __nv_bfloat162(l2, l3);
    }
#pragma unroll
    for (int off = 16; off > 0; off >>= 1) {
        da += __shfl_xor_sync(0xffffffffu, da, off);
        db += __shfl_xor_sync(0xffffffffu, db, off);
    }
    if (lane == 0) {
        a_out[tok] = sigmoidf_(da + ba[0]);
        b_out[tok] = sigmoidf_(db + bb[0]);
    }
}

// =============================================================================
// Tensor-core NT GEMM core (HMMA mma.sync, round-5 version).
// =============================================================================
__device__ __forceinline__ void ldsm4(uint32_t& r0, uint32_t& r1,
                                      uint32_t& r2, uint32_t& r3, uint32_t a)
{
    asm volatile("ldmatrix.sync.aligned.m8n8.x4.shared.b16 {%0,%1,%2,%3}, [%4];"
                 : "=r"(r0), "=r"(r1), "=r"(r2), "=r"(r3) : "r"(a));
}

__device__ __forceinline__ void mma16816(float c[4], const uint32_t a[4], const uint32_t b[2])
{
    asm volatile("mma.sync.aligned.m16n8k16.row.col.f32.bf16.bf16.f32 "
                 "{%0,%1,%2,%3}, {%4,%5,%6,%7}, {%8,%9}, {%0,%1,%2,%3};"
                 : "+f"(c[0]), "+f"(c[1]), "+f"(c[2]), "+f"(c[3])
                 : "r"(a[0]), "r"(a[1]), "r"(a[2]), "r"(a[3]), "r"(b[0]), "r"(b[1]));
}

template<int KDIM>
__device__ __forceinline__ void mma_loop(const bf16* __restrict__ A0,
                                         const bf16* __restrict__ A1,
                                         const bf16* __restrict__ A2,
                                         const bf16* __restrict__ B0,
                                         const bf16* __restrict__ B1,
                                         const bf16* __restrict__ B2,
                                         int m0, uint4* sA, uint4* sB,
                                         float acc[4][4][4])
{
    constexpr int KIT = KDIM / 32;
    constexpr int TOT = 3 * KIT;
    const int tid  = threadIdx.x;
    const int lane = tid & 31, warp = tid >> 5;
    const int wm = warp & 1, wn = warp >> 1;

    const int r0_ = tid >> 2,        u_ = tid & 3;
    const int r1_ = 64 + (tid >> 2);
    const int st0 = r0_ * 4 + (u_ ^ ((r0_ >> 1) & 3));
    const int st1 = r1_ * 4 + (u_ ^ ((r1_ >> 1) & 3));

    const uint32_t saB = (uint32_t)__cvta_generic_to_shared(sA);
    const uint32_t sbB = (uint32_t)__cvta_generic_to_shared(sB);

    uint4 ra0, ra1, rb0, rb1;
    {
        ra0 = *(const uint4*)(A0 + (size_t)(m0 + r0_) * KDIM + u_ * 8);
        ra1 = *(const uint4*)(A0 + (size_t)(m0 + r1_) * KDIM + u_ * 8);
        rb0 = *(const uint4*)(B0 + (size_t)r0_ * KDIM + u_ * 8);
        rb1 = *(const uint4*)(B0 + (size_t)r1_ * KDIM + u_ * 8);
    }

#pragma unroll 1
    for (int it = 0; it < TOT; ++it) {
        const int buf = it & 1;
        sA[buf * 512 + st0] = ra0; sA[buf * 512 + st1] = ra1;
        sB[buf * 512 + st0] = rb0; sB[buf * 512 + st1] = rb1;
        __syncthreads();

        if (it + 1 < TOT) {
            const int nit = it + 1;
            const int p = nit / KIT;
            const int kk = (nit - p * KIT) * 32;
            const bf16* Ap = (p == 0) ? A0 : (p == 1) ? A1 : A2;
            const bf16* Bp = (p == 0) ? B0 : (p == 1) ? B1 : B2;
            ra0 = *(const uint4*)(Ap + (size_t)(m0 + r0_) * KDIM + kk + u_ * 8);
            ra1 = *(const uint4*)(Ap + (size_t)(m0 + r1_) * KDIM + kk + u_ * 8);
            rb0 = *(const uint4*)(Bp + (size_t)r0_ * KDIM + kk + u_ * 8);
            rb1 = *(const uint4*)(Bp + (size_t)r1_ * KDIM + kk + u_ * 8);
        }

        const uint32_t aBase = saB + buf * 8192;
        const uint32_t bBase = sbB + buf * 8192;
#pragma unroll
        for (int ks = 0; ks < 2; ++ks) {
            uint32_t af[4][4], bfr[4][2];
#pragma unroll
            for (int mt = 0; mt < 4; ++mt) {
                const int row = wm * 64 + mt * 16 + (lane & 15);
                const int u = ks * 2 + (lane >> 4);
                ldsm4(af[mt][0], af[mt][1], af[mt][2], af[mt][3],
                      aBase + (uint32_t)((row * 4 + (u ^ ((row >> 1) & 3))) * 16));
            }
#pragma unroll
            for (int j = 0; j < 2; ++j) {
                const int gq = lane >> 3;
                const int n = wn * 32 + j * 16 + ((gq >> 1) << 3) + (lane & 7);
                const int u = ks * 2 + (gq & 1);
                uint32_t t0, t1, t2, t3;
                ldsm4(t0, t1, t2, t3,
                      bBase + (uint32_t)((n * 4 + (u ^ ((n >> 1) & 3))) * 16));
                bfr[j*2][0] = t0; bfr[j*2][1] = t1;
                bfr[j*2+1][0] = t2; bfr[j*2+1][1] = t3;
            }
#pragma unroll
            for (int mt = 0; mt < 4; ++mt)
#pragma unroll
                for (int nt = 0; nt < 4; ++nt)
                    mma16816(acc[mt][nt], af[mt], bfr[nt]);
        }
    }
}

// =============================================================================
// Fused 4-projection GEMM (HMMA).
// =============================================================================
__global__ __launch_bounds__(256, 2) void proj_gemm(
    const bf16* __restrict__ xh, const bf16* __restrict__ xl,
    const bf16* wqh, const bf16* wql, const bf16* wkh, const bf16* wkl,
    const bf16* wvh, const bf16* wvl, const bf16* wgh, const bf16* wgl,
    const float* bq, const float* bk, const float* bv, const float* bg,
    float* outq, float* outk, float* outv, float* outg)
{
    __shared__ uint4 sA[1024];
    __shared__ uint4 sB[1024];
    __shared__ float snorm[4][128];

    const int proj = blockIdx.x;
    const int m0 = blockIdx.y * 128;
    const bf16 *Bh, *Bl; const float* bias; float* C;
    if      (proj == 0) { Bh = wqh; Bl = wql; bias = bq; C = outq; }
    else if (proj == 1) { Bh = wkh; Bl = wkl; bias = bk; C = outk; }
    else if (proj == 2) { Bh = wvh; Bl = wvl; bias = bv; C = outv; }
    else                { Bh = wgh; Bl = wgl; bias = bg; C = outg; }

    float acc[4][4][4];
#pragma unroll
    for (int mt = 0; mt < 4; ++mt)
#pragma unroll
        for (int nt = 0; nt < 4; ++nt)
#pragma unroll
            for (int c = 0; c < 4; ++c) acc[mt][nt][c] = 0.0f;

    mma_loop<D_>(xh, xh, xl, Bh, Bl, Bh, m0, sA, sB, acc);

    const int lane = threadIdx.x & 31, warp = threadIdx.x >> 5;
    const int wm = warp & 1, wn = warp >> 1;

#pragma unroll
    for (int nt = 0; nt < 4; ++nt) {
        const int col = wn * 32 + nt * 8 + (lane & 3) * 2;
        const float b0 = bias[col], b1 = bias[col + 1];
#pragma unroll
        for (int mt = 0; mt < 4; ++mt) {
            acc[mt][nt][0] += b0; acc[mt][nt][1] += b1;
            acc[mt][nt][2] += b0; acc[mt][nt][3] += b1;
        }
    }

    if (proj == 3) {
#pragma unroll
        for (int mt = 0; mt < 4; ++mt)
#pragma unroll
            for (int nt = 0; nt < 4; ++nt)
#pragma unroll
                for (int c = 0; c < 4; ++c)
                    acc[mt][nt][c] = sigmoidf_(acc[mt][nt][c]);
    }

    if (proj == 1) {
#pragma unroll
        for (int mt = 0; mt < 4; ++mt)
#pragma unroll
            for (int h = 0; h < 2; ++h) {
                float ss = 0.0f;
#pragma unroll
                for (int nt = 0; nt < 4; ++nt) {
                    ss += acc[mt][nt][2*h] * acc[mt][nt][2*h];
                    ss += acc[mt][nt][2*h+1] * acc[mt][nt][2*h+1];
                }
                ss += __shfl_xor_sync(0xffffffffu, ss, 1);
                ss += __shfl_xor_sync(0xffffffffu, ss, 2);
                if ((lane & 3) == 0)
                    snorm[wn][wm*64 + mt*16 + h*8 + (lane >> 2)] = ss;
            }
        __syncthreads();
#pragma unroll
        for (int mt = 0; mt < 4; ++mt)
#pragma unroll
            for (int h = 0; h < 2; ++h) {
                const int row = wm*64 + mt*16 + h*8 + (lane >> 2);
                const float s = snorm[0][row] + snorm[1][row] + snorm[2][row] + snorm[3][row];
                const float inv = 1.0f / fmaxf(sqrtf(s), 1e-12f);
#pragma unroll
                for (int nt = 0; nt < 4; ++nt) {
                    acc[mt][nt][2*h]   *= inv;
                    acc[mt][nt][2*h+1] *= inv;
                }
            }
    }

#pragma unroll
    for (int mt = 0; mt < 4; ++mt) {
        const int r = m0 + wm*64 + mt*16 + (lane >> 2);
#pragma unroll
        for (int nt = 0; nt < 4; ++nt) {
            const int col = wn*32 + nt*8 + (lane & 3)*2;
            *(float2*)(C + (size_t)r * C_ + col)       = make_float2(acc[mt][nt][0], acc[mt][nt][1]);
            *(float2*)(C + (size_t)(r+8) * C_ + col)   = make_float2(acc[mt][nt][2], acc[mt][nt][3]);
        }
    }
}

// =============================================================================
// Output GEMM (HMMA).
// =============================================================================
__global__ __launch_bounds__(256, 2) void out_gemm(
    const bf16* __restrict__ oh, const bf16* __restrict__ ol,
    const bf16* __restrict__ woh, const bf16* __restrict__ wol,
    const float* __restrict__ bo, float* __restrict__ out)
{
    __shared__ uint4 sA[1024];
    __shared__ uint4 sB[1024];

    const int n0 = blockIdx.x * 128;
    const int m0 = blockIdx.y * 128;
    const bf16* Bh = woh + (size_t)n0 * C_;
    const bf16* Bl = wol + (size_t)n0 * C_;

    float acc[4][4][4];
#pragma unroll
    for (int mt = 0; mt < 4; ++mt)
#pragma unroll
        for (int nt = 0; nt < 4; ++nt)
#pragma unroll
            for (int c = 0; c < 4; ++c) acc[mt][nt][c] = 0.0f;

    mma_loop<C_>(oh, oh, ol, Bh, Bl, Bh, m0, sA, sB, acc);

    const int lane = threadIdx.x & 31, warp = threadIdx.x >> 5;
    const int wm = warp & 1, wn = warp >> 1;

#pragma unroll
    for (int mt = 0; mt < 4; ++mt) {
        const int r = m0 + wm*64 + mt*16 + (lane >> 2);
#pragma unroll
        for (int nt = 0; nt < 4; ++nt) {
            const int col = n0 + wn*32 + nt*8 + (lane & 3)*2;
            const float b0 = bo[col], b1 = bo[col + 1];
            *(float2*)(out + (size_t)r * D_ + col)
                = make_float2(acc[mt][nt][0] + b0, acc[mt][nt][1] + b1);
            *(float2*)(out + (size_t)(r+8) * D_ + col)
                = make_float2(acc[mt][nt][2] + b0, acc[mt][nt][3] + b1);
        }
    }
}

// =============================================================================
// Gram precompute: per chunk, G[s][tau] = k_s . k_tau (6 values), fp32.
// One warp per chunk; 8 chunks per CTA.
// =============================================================================
__global__ __launch_bounds__(256) void gram_kernel(const float* __restrict__ k,
                                                   float* __restrict__ gram)
{
    const int warp = threadIdx.x >> 5, lane = threadIdx.x & 31;
    const int cid = blockIdx.x * 8 + warp;      // 0 .. B_*NCH-1
    const int bb = cid >> 10, tc = cid & 1023;
    const float* kg = k + ((size_t)bb * T_ + (size_t)tc * LCH) * C_ + lane * 4;

    float4 k0 = *(const float4*)(kg + 0*C_);
    float4 k1 = *(const float4*)(kg + 1*C_);
    float4 k2 = *(const float4*)(kg + 2*C_);
    float4 k3 = *(const float4*)(kg + 3*C_);

    float G01 = k0.x*k1.x + k0.y*k1.y + k0.z*k1.z + k0.w*k1.w;
    float G02 = k0.x*k2.x + k0.y*k2.y + k0.z*k2.z + k0.w*k2.w;
    float G03 = k0.x*k3.x + k0.y*k3.y + k0.z*k3.z + k0.w*k3.w;
    float G12 = k1.x*k2.x + k1.y*k2.y + k1.z*k2.z + k1.w*k2.w;
    float G13 = k1.x*k3.x + k1.y*k3.y + k1.z*k3.z + k1.w*k3.w;
    float G23 = k2.x*k3.x + k2.y*k3.y + k2.z*k3.z + k2.w*k3.w;

#pragma unroll
    for (int off = 16; off > 0; off >>= 1) {
        G01 += __shfl_xor_sync(0xffffffffu, G01, off);
        G02 += __shfl_xor_sync(0xffffffffu, G02, off);
        G03 += __shfl_xor_sync(0xffffffffu, G03, off);
        G12 += __shfl_xor_sync(0xffffffffu, G12, off);
        G13 += __shfl_xor_sync(0xffffffffu, G13, off);
        G23 += __shfl_xor_sync(0xffffffffu, G23, off);
    }
    if (lane == 0) {
        float* gp = gram + (size_t)cid * 8;
        *(float4*)(gp)     = make_float4(G01, G02, G03, G12);
        *(float4*)(gp + 4) = make_float4(G13, G23, 0.0f, 0.0f);
    }
}

// =============================================================================
// Chunked (L=4) gated delta-rule recurrence, GROUPS=16, one row per warp.
// Gram matrix precomputed -> only 4 in-loop warp reductions per chunk.
// =============================================================================
struct ChunkRegs {
    float k[LCH][4];
    float q[LCH], v[LCH], a[LCH], b[LCH];
    float G[6];
};

__device__ __forceinline__ float red32(float x) {
    x += __shfl_xor_sync(0xffffffffu, x, 1);
    x += __shfl_xor_sync(0xffffffffu, x, 2);
    x += __shfl_xor_sync(0xffffffffu, x, 4);
    x += __shfl_xor_sync(0xffffffffu, x, 8);
    x += __shfl_xor_sync(0xffffffffu, x, 16);
    return x;
}

__device__ __forceinline__ void load_chunk(int tcN,
                                           const float* __restrict__ kg,
                                           const float* __restrict__ qg,
                                           const float* __restrict__ vg,
                                           const float* __restrict__ ag,
                                           const float* __restrict__ bg,
                                           const float* __restrict__ gramb,
                                           int i, int jb, ChunkRegs& R)
{
#pragma unroll
    for (int t4 = 0; t4 < LCH; ++t4) {
        const size_t off = ((size_t)tcN*LCH + t4) * C_;
        float4 kx = *(const float4*)(kg + off + jb);
        R.k[t4][0]=kx.x; R.k[t4][1]=kx.y; R.k[t4][2]=kx.z; R.k[t4][3]=kx.w;
        R.q[t4] = qg[off + i];
        R.v[t4] = vg[off + i];
    }
    float4 a4 = *(const float4*)(ag + tcN*LCH);
    float4 b4 = *(const float4*)(bg + tcN*LCH);
    R.a[0]=a4.x; R.a[1]=a4.y; R.a[2]=a4.z; R.a[3]=a4.w;
    R.b[0]=b4.x; R.b[1]=b4.y; R.b[2]=b4.z; R.b[3]=b4.w;
    float4 ga = *(const float4*)(gramb + (size_t)tcN * 8);
    float4 gb = *(const float4*)(gramb + (size_t)tcN * 8 + 4);
    R.G[0]=ga.x; R.G[1]=ga.y; R.G[2]=ga.z; R.G[3]=ga.w;
    R.G[4]=gb.x; R.G[5]=gb.y;
}

__device__ __forceinline__ void chunk_body(int tc, int buf, bool pf,
                                           float S[4], ChunkRegs& cur, ChunkRegs& nxt,
                                           const float* __restrict__ kg,
                                           const float* __restrict__ qg,
                                           const float* __restrict__ vg,
                                           const float* __restrict__ ag,
                                           const float* __restrict__ bg,
                                           const float* __restrict__ gramb,
                                           float* __restrict__ op,
                                           int i, int jb, int warp, int lane, int tid,
                                           float (*osh)[LCH][8][C_])
{
    // --- phase 1: m partials vs chunk-start S (Gram precomputed) ---
    float m[LCH];
#pragma unroll
    for (int t4 = 0; t4 < LCH; ++t4) {
        float s = 0.0f;
#pragma unroll
        for (int jj = 0; jj < 4; ++jj) s += S[jj] * cur.k[t4][jj];
        m[t4] = s;
    }

    // --- prefetch next chunk while reduces are in flight ---
    if (pf) load_chunk(tc + 1, kg, qg, vg, ag, bg, gramb, i, jb, nxt);

    // --- 4 independent full-warp reductions ---
    m[0]=red32(m[0]); m[1]=red32(m[1]); m[2]=red32(m[2]); m[3]=red32(m[3]);

    // --- phase 2: exact scalar recursion for c_tau ---
    const float a0=cur.a[0], a1=cur.a[1], a2=cur.a[2], a3=cur.a[3];
    const float G01=cur.G[0], G02=cur.G[1], G03=cur.G[2];
    const float G12=cur.G[3], G13=cur.G[4], G23=cur.G[5];
    const float u0 = m[0];
    const float c0 = cur.b[0] * (cur.v[0] - a0*u0);
    const float u1 = a0*m[1] + c0*G01;
    const float c1 = cur.b[1] * (cur.v[1] - a1*u1);
    const float a01 = a0*a1;
    const float u2 = a01*m[2] + a1*c0*G02 + c1*G12;
    const float c2 = cur.b[2] * (cur.v[2] - a2*u2);
    const float u3 = a01*a2*m[3] + a1*a2*c0*G03 + a2*c1*G13 + c2*G23;
    const float c3 = cur.b[3] * (cur.v[3] - a3*u3);
    const float cc[LCH] = {c0, c1, c2, c3};

    // --- phase 3: per-step register updates + o partials (no shuffles) ---
#pragma unroll
    for (int t4 = 0; t4 < LCH; ++t4) {
        float po[4];
#pragma unroll
        for (int jj = 0; jj < 4; ++jj) {
            S[jj] = cur.a[t4] * S[jj] + cc[t4] * cur.k[t4][jj];
            po[jj] = cur.q[t4] * S[jj];
        }
        *(float4*)&osh[buf][t4][warp][lane * 4] = make_float4(po[0], po[1], po[2], po[3]);
    }
    __syncthreads();   // single barrier per chunk (osh double-buffered)

    // --- phase 4: cross-warp float4 sum + global write (128 threads) ---
    if (tid < 128) {
        const int t4 = tid >> 5, c4 = (tid & 31) * 4;
        float4 acc = *(const float4*)&osh[buf][t4][0][c4];
#pragma unroll
        for (int w = 1; w < 8; ++w) {
            const float4 p = *(const float4*)&osh[buf][t4][w][c4];
            acc.x += p.x; acc.y += p.y; acc.z += p.z; acc.w += p.w;
        }
        *(float4*)(op + ((size_t)tc*LCH + t4) * C_ + c4) = acc;
    }
}

__global__ __launch_bounds__(256, 2) void recurrence4(const float* __restrict__ q,
                                                      const float* __restrict__ k,
                                                      const float* __restrict__ v,
                                                      const float* __restrict__ al,
                                                      const float* __restrict__ be,
                                                      const float* __restrict__ gram,
                                                      float* __restrict__ opart)
{
    const int g   = blockIdx.x;
    const int bb  = blockIdx.y;
    const int tid = threadIdx.x;
    const int warp = tid >> 5, lane = tid & 31;
    const int i  = g * 8 + warp;
    const int jb = lane * 4;

    __shared__ __align__(16) float osh[2][LCH][8][C_];

    const size_t bbase = (size_t)bb * T_ * C_;
    const size_t sbase = (size_t)bb * T_;
    const float* kg = k + bbase;
    const float* qg = q + bbase;
    const float* vg = v + bbase;
    const float* ag = al + sbase;
    const float* bg = be + sbase;
    const float* gramb = gram + (size_t)bb * NCH * 8;
    float* op = opart + (size_t)g * M_ * C_ + bbase;

    float S[4];
#pragma unroll
    for (int jj = 0; jj < 4; ++jj) S[jj] = 0.0f;

    ChunkRegs RA, RB;
    load_chunk(0, kg, qg, vg, ag, bg, gramb, i, jb, RA);

#pragma unroll 1
    for (int tc = 0; tc < NCH; tc += 2) {
        chunk_body(tc,   0, true,           S, RA, RB, kg, qg, vg, ag, bg, gramb, op, i, jb, warp, lane, tid, osh);
        chunk_body(tc+1, 1, (tc+2) < NCH,   S, RB, RA, kg, qg, vg, ag, bg, gramb, op, i, jb, warp, lane, tid, osh);
    }
}

// =============================================================================
// combine: o = (sum over groups of opart) * gate -> bf16 hi/lo split
// =============================================================================
__global__ __launch_bounds__(256) void combine_split(const float* __restrict__ opart,
                                                     const float* __restrict__ gate,
                                                     bf16* __restrict__ oh,
                                                     bf16* __restrict__ ol)
{
    const size_t idx = ((size_t)blockIdx.x * 256 + threadIdx.x) * 4;
    float4 s = make_float4(0.f, 0.f, 0.f, 0.f);
#pragma unroll
    for (int g = 0; g < GROUPS; ++g) {
        float4 p = *(const float4*)(opart + (size_t)g * M_ * C_ + idx);
        s.x += p.x; s.y += p.y; s.z += p.z; s.w += p.w;
    }
    float4 gt = *(const float4*)(gate + idx);
    s.x *= gt.x; s.y *= gt.y; s.z *= gt.z; s.w *= gt.w;

    bf16 h0 = __float2bfloat16_rn(s.x);
    bf16 h1 = __float2bfloat16_rn(s.y);
    bf16 h2 = __float2bfloat16_rn(s.z);
    bf16 h3 = __float2bfloat16_rn(s.w);
    bf16 l0 = __float2bfloat16_rn(s.x - __bfloat162float(h0));
    bf16 l1 = __float2bfloat16_rn(s.y - __bfloat162float(h1));
    bf16 l2 = __float2bfloat16_rn(s.z - __bfloat162float(h2));
    bf16 l3 = __float2bfloat16_rn(s.w - __bfloat162float(h3));
    __nv_bfloat162* H = (__nv_bfloat162*)(oh + idx);
    __nv_bfloat162* L = (__nv_bfloat162*)(ol + idx);
    H[0] = __nv_bfloat162(h0, h1); H[1] = __nv_bfloat162(h2, h3);
    L[0] = __nv_bfloat162(l0, l1); L[1] = __nv_bfloat162(l2, l3);
}

// =============================================================================
extern "C" void kernel_launch(void* const* d_in, const int* in_sizes, int n_in,
                              void* d_out, int out_size)
{
    const float* x  = (const float*)d_in[0];
    const float* Wq = (const float*)d_in[1];
    const float* bq = (const float*)d_in[2];
    const float* Wk = (const float*)d_in[3];
    const float* bk = (const float*)d_in[4];
    const float* Wv = (const float*)d_in[5];
    const float* bv = (const float*)d_in[6];
    const float* Wa = (const float*)d_in[7];
    const float* ba = (const float*)d_in[8];
    const float* Wb = (const float*)d_in[9];
    const float* bb = (const float*)d_in[10];
    const float* Wg = (const float*)d_in[11];
    const float* bg = (const float*)d_in[12];
    const float* Wo = (const float*)d_in[13];
    const float* bo = (const float*)d_in[14];
    float* out = (float*)d_out;

    float *q, *k, *v, *g, *a, *b, *op, *gram;
    bf16 *xh, *xl, *oh, *ol;
    bf16 *wqh, *wql, *wkh, *wkl, *wvh, *wvl, *wgh, *wgl, *woh, *wol;
    cudaGetSymbolAddress((void**)&q,  g_q);
    cudaGetSymbolAddress((void**)&k,  g_k);
    cudaGetSymbolAddress((void**)&v,  g_v);
    cudaGetSymbolAddress((void**)&g,  g_g);
    cudaGetSymbolAddress((void**)&a,  g_a);
    cudaGetSymbolAddress((void**)&b,  g_b);
    cudaGetSymbolAddress((void**)&op, g_opart);
    cudaGetSymbolAddress((void**)&gram, g_gram);
    cudaGetSymbolAddress((void**)&xh, g_xh);
    cudaGetSymbolAddress((void**)&xl, g_xl);
    cudaGetSymbolAddress((void**)&oh, g_oh);
    cudaGetSymbolAddress((void**)&ol, g_ol);
    cudaGetSymbolAddress((void**)&wqh, g_wqh); cudaGetSymbolAddress((void**)&wql, g_wql);
    cudaGetSymbolAddress((void**)&wkh, g_wkh); cudaGetSymbolAddress((void**)&wkl, g_wkl);
    cudaGetSymbolAddress((void**)&wvh, g_wvh); cudaGetSymbolAddress((void**)&wvl, g_wvl);
    cudaGetSymbolAddress((void**)&wgh, g_wgh); cudaGetSymbolAddress((void**)&wgl, g_wgl);
    cudaGetSymbolAddress((void**)&woh, g_woh); cudaGetSymbolAddress((void**)&wol, g_wol);

    const dim3 blk(256);

    // (0) fused prep: alpha/beta + x split + 5 weight splits
    fused_prep<<<M_/8 + 5*128, blk>>>(x, Wa, ba, Wb, bb, a, b, xh, xl,
                                      Wq, Wk, Wv, Wg, Wo,
                                      wqh, wql, wkh, wkl, wvh, wvl,
                                      wgh, wgl, woh, wol);

    // (1) fused 4-projection HMMA GEMM (k-norm + gate-sigmoid in epilogue)
    proj_gemm<<<dim3(4, M_/128), blk>>>(xh, xl,
                                        wqh, wql, wkh, wkl, wvh, wvl, wgh, wgl,
                                        bq, bk, bv, bg, q, k, v, g);

    // (2) chunk Gram precompute
    gram_kernel<<<B_*NCH/8, blk>>>(k, gram);

    // (3) chunked sequential recurrence (256 CTAs)  <- ncu profiles this one
    recurrence4<<<dim3(GROUPS, B_), blk>>>(q, k, v, a, b, gram, op);

    // (4) group-sum + gate -> bf16 split
    combine_split<<<(M_*C_/4)/256, blk>>>(op, g, oh, ol);

    // (5) output projection (HMMA)
    out_gemm<<<dim3(D_/128, M_/128), blk>>>(oh, ol, woh, wol, bo, out);
}